// round 3
// baseline (speedup 1.0000x reference)
#include <cuda_runtime.h>

#define BB   8
#define CC   64
#define TT   192
#define FFR  128
#define LTm  192               // time view L
#define LFm  128               // freq view L
#define DTm  (CC*FFR)          // 8192
#define DFm  (CC*TT)           // 12288
#define NEL  (BB*CC*TT*FFR)    // 12,582,912
#define HH   4

// ---------------- scratch (device globals; no allocations) ----------------
__device__ float g_XT[2][NEL];                  // transposed time-view X for s,t
__device__ float g_G[2][2][BB*LTm*LTm];         // [view][which] gram -> overwritten with logPs / Pt_row
__device__ float g_inv[2][2][BB*LTm];           // 1/max(norm,eps)
__device__ float g_mean[2][2][BB*LTm];          // row means of P
__device__ float g_ent[2][BB*LTm];              // entropy terms (t side)
__device__ float g_qk[2][2][BB*LTm*HH];         // q (sel=0), k (sel=1)
__device__ float g_alpha[2][BB*LTm*LTm];
__device__ float g_colsum[2][BB*LTm];
__device__ float g_part[2][256];

// ---------------- small helpers ----------------
__device__ __forceinline__ float warpSum(float v) {
#pragma unroll
    for (int o = 16; o; o >>= 1) v += __shfl_xor_sync(0xffffffffu, v, o);
    return v;
}
__device__ __forceinline__ float warpMax(float v) {
#pragma unroll
    for (int o = 16; o; o >>= 1) v = fmaxf(v, __shfl_xor_sync(0xffffffffu, v, o));
    return v;
}
__device__ __forceinline__ float blockSum(float v, float* sm) {
    v = warpSum(v);
    int w = threadIdx.x >> 5;
    __syncthreads();
    if ((threadIdx.x & 31) == 0) sm[w] = v;
    __syncthreads();
    float r = 0.f;
    int nw = (blockDim.x + 31) >> 5;
    for (int i = 0; i < nw; i++) r += sm[i];
    return r;
}
__device__ __forceinline__ float blockMax(float v, float* sm) {
    v = warpMax(v);
    int w = threadIdx.x >> 5;
    __syncthreads();
    if ((threadIdx.x & 31) == 0) sm[w] = v;
    __syncthreads();
    float r = -3.402823466e38f;
    int nw = (blockDim.x + 31) >> 5;
    for (int i = 0; i < nw; i++) r = fmaxf(r, sm[i]);
    return r;
}

union Cvt { unsigned long long u; float2 f; };

__device__ __forceinline__ void lds_v2u64(unsigned long long& x, unsigned long long& y, unsigned addr) {
    asm volatile("ld.shared.v2.u64 {%0,%1}, [%2];" : "=l"(x), "=l"(y) : "r"(addr));
}
__device__ __forceinline__ void fma2(unsigned long long& d, unsigned long long a, unsigned long long b) {
    asm volatile("fma.rn.f32x2 %0, %1, %2, %0;" : "+l"(d) : "l"(a), "l"(b));
}

// ---------------- 1) transpose feat (B,C,T,Fr) -> (B,C,Fr,T), both tensors ----------------
__global__ void transpose_kernel(const float* __restrict__ fs, const float* __restrict__ ft) {
    __shared__ float tile[32][33];
    int z = blockIdx.z;
    int which = z >> 9;            // 0..511 -> fs, 512..1023 -> ft
    int bc = z & 511;
    const float* in = which ? ft : fs;
    int t0 = blockIdx.x * 32, f0 = blockIdx.y * 32;
    const float* src = in + (size_t)bc * TT * FFR;
    float* out = g_XT[which] + (size_t)bc * TT * FFR;
    int tx = threadIdx.x, ty = threadIdx.y;
#pragma unroll
    for (int i = 0; i < 32; i += 8)
        tile[ty + i][tx] = src[(size_t)(t0 + ty + i) * FFR + f0 + tx];
    __syncthreads();
#pragma unroll
    for (int i = 0; i < 32; i += 8)
        out[(size_t)(f0 + ty + i) * TT + t0 + tx] = tile[tx][ty + i];
}

// ---------------- 2) fused SYRK: G = X X^T (both views, one wave) ----------------
// X[row, k] at base + k*L + row (unit row stride). 64x64 output tile per block,
// triangular tile pairs only (mirror written). Inner math = packed fp32x2 FMA.
__global__ void __launch_bounds__(256, 1) gram_kernel(const float* __restrict__ fs,
                                                      const float* __restrict__ ft) {
    int idx = blockIdx.x;
    int view, p, b, which, L, D, nt;
    if (idx < 96) { view = 0; L = LTm; D = DTm; nt = 3; p = idx % 6; b = (idx / 6) & 7; which = idx / 48; }
    else { int r = idx - 96; view = 1; L = LFm; D = DFm; nt = 2; p = r % 3; b = (r / 3) & 7; which = r / 24; }

    int pi = 0, rem = p, rl = nt;
    while (rem >= rl) { rem -= rl; pi++; rl--; }
    int pj = pi + rem;
    int i0 = pi * 64, j0 = pj * 64;

    const float* X;
    if (view == 0) X = g_XT[which];
    else           X = which ? ft : fs;
    X += (size_t)b * L * D;
    float* G = g_G[view][which] + (size_t)b * L * L;

    __shared__ __align__(16) float sA[32 * 128];   // duplicated: (v,v) per element, k-major
    __shared__ __align__(16) float sB[32 * 64];    // k-major

    int tid = threadIdx.x;
    int lr = tid & 63, lk = tid >> 6;              // loader mapping: row fast (coalesced)
    const float* pa = X + i0 + lr;
    const float* pb = X + j0 + lr;
    int nch = D >> 5;

    float ra[8], rb[8];
#pragma unroll
    for (int q = 0; q < 8; q++) {
        int kk = lk * 8 + q;
        ra[q] = pa[(size_t)kk * L];
        rb[q] = pb[(size_t)kk * L];
    }

    int tx = tid & 15, ty = tid >> 4;
    unsigned long long acc[4][2];
#pragma unroll
    for (int u = 0; u < 4; u++) { acc[u][0] = 0ull; acc[u][1] = 0ull; }

    unsigned sAb = (unsigned)__cvta_generic_to_shared(sA);
    unsigned sBb = (unsigned)__cvta_generic_to_shared(sB);
    unsigned aBase = sAb + (unsigned)ty * 32;
    unsigned bBase = sBb + (unsigned)tx * 16;

    for (int ch = 0; ; ch++) {
        __syncthreads();
#pragma unroll
        for (int q = 0; q < 8; q++) {
            int kk = lk * 8 + q;
            ((float2*)sA)[kk * 64 + lr] = make_float2(ra[q], ra[q]);
            sB[kk * 64 + lr] = rb[q];
        }
        __syncthreads();
        bool more = (ch + 1 < nch);
        if (more) {
            const float* pa2 = pa + (size_t)(ch + 1) * 32 * L;
            const float* pb2 = pb + (size_t)(ch + 1) * 32 * L;
#pragma unroll
            for (int q = 0; q < 8; q++) {
                int kk = lk * 8 + q;
                ra[q] = pa2[(size_t)kk * L];
                rb[q] = pb2[(size_t)kk * L];
            }
        }
#pragma unroll
        for (int kk = 0; kk < 32; kk++) {
            unsigned long long a0, a1, a2, a3, b01, b23;
            lds_v2u64(a0, a1, aBase + kk * 512);
            lds_v2u64(a2, a3, aBase + kk * 512 + 16);
            lds_v2u64(b01, b23, bBase + kk * 256);
            fma2(acc[0][0], a0, b01); fma2(acc[0][1], a0, b23);
            fma2(acc[1][0], a1, b01); fma2(acc[1][1], a1, b23);
            fma2(acc[2][0], a2, b01); fma2(acc[2][1], a2, b23);
            fma2(acc[3][0], a3, b01); fma2(acc[3][1], a3, b23);
        }
        if (!more) break;
    }

#pragma unroll
    for (int u = 0; u < 4; u++) {
        Cvt c0, c1; c0.u = acc[u][0]; c1.u = acc[u][1];
        int i = i0 + ty * 4 + u;
        float4 v4 = make_float4(c0.f.x, c0.f.y, c1.f.x, c1.f.y);
        *(float4*)&G[(size_t)i * L + j0 + tx * 4] = v4;
        if (pi != pj) {
            int j = j0 + tx * 4;
            G[(size_t)(j + 0) * L + i] = v4.x;
            G[(size_t)(j + 1) * L + i] = v4.y;
            G[(size_t)(j + 2) * L + i] = v4.z;
            G[(size_t)(j + 3) * L + i] = v4.w;
        }
    }
}

// ---------------- 3) inverse norms from gram diagonal ----------------
__global__ void norms_kernel(int view, int L) {
    int b = blockIdx.x, which = blockIdx.y, l = threadIdx.x;
    float g = g_G[view][which][(size_t)b * L * L + (size_t)l * L + l];
    g_inv[view][which][b * L + l] = 1.0f / fmaxf(sqrtf(g), 1e-8f);
}

// ---------------- 4) per-row: P, rowmean, softmax(+eps), log / entropy (in place) ----------------
__global__ void rowproc_kernel(int view, int L) {
    __shared__ float red[8];
    int l = blockIdx.x, b = blockIdx.y, which = blockIdx.z;
    int m = threadIdx.x;
    float* G = g_G[view][which] + (size_t)b * L * L + (size_t)l * L;
    float invl = g_inv[view][which][b * L + l];
    float invm = g_inv[view][which][b * L + m];
    float pv = 0.5f * (G[m] * invl * invm + 1.0f);

    float s = blockSum(pv, red);
    if (m == 0) g_mean[view][which][b * L + l] = s / (float)L;

    float mx = blockMax(pv, red);
    float e = expf(pv - mx);
    float Z = blockSum(e, red);
    float sp = e / Z + 1e-8f;                    // P_row = softmax + EPS

    if (which == 0) {
        G[m] = logf(sp + 1e-8f);                 // logPs = log(P_row + EPS)  (EPS twice, matches ref)
    } else {
        G[m] = sp;                               // Pt_row
        float ent = blockSum(sp * logf(sp + 1e-8f), red);   // sum Pt*log(Pt+EPS)
        if (m == 0) g_ent[view][b * L + l] = ent;
    }
}

// ---------------- 5) tiny MLP (Linear(1,H)+ReLU+LayerNorm) ----------------
__global__ void mlp_kernel(int view, int L,
                           const float* __restrict__ Wq, const float* __restrict__ bq,
                           const float* __restrict__ gq, const float* __restrict__ Bq,
                           const float* __restrict__ Wk, const float* __restrict__ bk,
                           const float* __restrict__ gk, const float* __restrict__ Bk) {
    int b = blockIdx.x, sel = blockIdx.y;       // 0: q from s-means, 1: k from t-means
    int l = threadIdx.x;
    const float* W  = sel ? Wk : Wq;
    const float* bi = sel ? bk : bq;
    const float* gg = sel ? gk : gq;
    const float* be = sel ? Bk : Bq;
    float x = g_mean[view][sel][b * L + l];
    float h[HH]; float mu = 0.f;
#pragma unroll
    for (int j = 0; j < HH; j++) { h[j] = fmaxf(W[j] * x + bi[j], 0.f); mu += h[j]; }
    mu *= (1.0f / HH);
    float var = 0.f;
#pragma unroll
    for (int j = 0; j < HH; j++) { float d = h[j] - mu; var += d * d; }
    var *= (1.0f / HH);
    float inv = rsqrtf(var + 1e-5f);
#pragma unroll
    for (int j = 0; j < HH; j++)
        g_qk[view][sel][((size_t)b * L + l) * HH + j] = gg[j] * (h[j] - mu) * inv + be[j];
}

// ---------------- 6) alpha = softmax(q k^T / sqrt(H+eps)) ----------------
__global__ void alpha_kernel(int view, int L) {
    __shared__ float kb[LTm * HH];
    __shared__ float red[8];
    int s = blockIdx.x, b = blockIdx.y;
    int t = threadIdx.x;
    for (int i = t; i < L * HH; i += blockDim.x)
        kb[i] = g_qk[view][1][(size_t)b * L * HH + i];
    float q0 = g_qk[view][0][((size_t)b * L + s) * HH + 0];
    float q1 = g_qk[view][0][((size_t)b * L + s) * HH + 1];
    float q2 = g_qk[view][0][((size_t)b * L + s) * HH + 2];
    float q3 = g_qk[view][0][((size_t)b * L + s) * HH + 3];
    __syncthreads();
    float invScale = rsqrtf(4.0f + 1e-8f);
    float a = (q0 * kb[t * 4 + 0] + q1 * kb[t * 4 + 1] + q2 * kb[t * 4 + 2] + q3 * kb[t * 4 + 3]) * invScale;
    float mx = blockMax(a, red);
    float e = expf(a - mx);
    float Z = blockSum(e, red);
    g_alpha[view][(size_t)b * L * L + (size_t)s * L + t] = e / Z;
}

// ---------------- 7) column sums of alpha ----------------
__global__ void colsum_kernel(int view, int L) {
    int b = blockIdx.x, t = threadIdx.x;
    const float* al = g_alpha[view] + (size_t)b * L * L;
    float s = 0.f;
    for (int ss = 0; ss < L; ss++) s += al[(size_t)ss * L + t];
    g_colsum[view][b * L + t] = s;
}

// ---------------- 8) term2 partials: sum_{s,k} logPs[s,k] * (alpha @ Pt_row)[s,k] ----------------
__global__ void part_kernel(int view, int L) {
    __shared__ float sal[8][LTm];
    __shared__ float red[8];
    int b = blockIdx.y, s0 = blockIdx.x * 8;
    const float* logPs = g_G[view][0] + (size_t)b * L * L;
    const float* Pt    = g_G[view][1] + (size_t)b * L * L;
    const float* al    = g_alpha[view] + (size_t)b * L * L;
    int k = threadIdx.x;
#pragma unroll
    for (int i = 0; i < 8; i++) sal[i][k] = al[(size_t)(s0 + i) * L + k];
    __syncthreads();
    float m[8];
#pragma unroll
    for (int i = 0; i < 8; i++) m[i] = 0.f;
    for (int t = 0; t < L; t++) {
        float pv = Pt[(size_t)t * L + k];
#pragma unroll
        for (int i = 0; i < 8; i++) m[i] += sal[i][t] * pv;
    }
    float acc = 0.f;
#pragma unroll
    for (int i = 0; i < 8; i++) acc += m[i] * logPs[(size_t)(s0 + i) * L + k];
    float tot = blockSum(acc, red);
    if (k == 0) g_part[view][blockIdx.y * gridDim.x + blockIdx.x] = tot;
}

// ---------------- 9) final deterministic reduction ----------------
__global__ void final_kernel(float* out) {
    __shared__ float red[8];
    int tid = threadIdx.x;
    float t2T = 0.f; for (int i = tid; i < (LTm / 8) * BB; i += 256) t2T += g_part[0][i];
    t2T = blockSum(t2T, red);
    float t2F = 0.f; for (int i = tid; i < (LFm / 8) * BB; i += 256) t2F += g_part[1][i];
    t2F = blockSum(t2F, red);
    float t1T = 0.f; for (int i = tid; i < BB * LTm; i += 256) t1T += g_ent[0][i] * g_colsum[0][i];
    t1T = blockSum(t1T, red);
    float t1F = 0.f; for (int i = tid; i < BB * LFm; i += 256) t1F += g_ent[1][i] * g_colsum[1][i];
    t1F = blockSum(t1F, red);
    if (tid == 0) {
        float lt = (t1T - t2T) / ((float)BB * LTm * LTm + 1e-8f);
        float lf = (t1F - t2F) / ((float)BB * LFm * LFm + 1e-8f);
        out[0] = lt + lf;
    }
}

// ---------------- launch ----------------
extern "C" void kernel_launch(void* const* d_in, const int* in_sizes, int n_in,
                              void* d_out, int out_size) {
    const float* fs  = (const float*)d_in[0];
    const float* ft  = (const float*)d_in[1];
    const float* WqT = (const float*)d_in[2];
    const float* bqT = (const float*)d_in[3];
    const float* gqT = (const float*)d_in[4];
    const float* BqT = (const float*)d_in[5];
    const float* WkT = (const float*)d_in[6];
    const float* bkT = (const float*)d_in[7];
    const float* gkT = (const float*)d_in[8];
    const float* BkT = (const float*)d_in[9];
    const float* WqF = (const float*)d_in[10];
    const float* bqF = (const float*)d_in[11];
    const float* gqF = (const float*)d_in[12];
    const float* BqF = (const float*)d_in[13];
    const float* WkF = (const float*)d_in[14];
    const float* bkF = (const float*)d_in[15];
    const float* gkF = (const float*)d_in[16];
    const float* BkF = (const float*)d_in[17];
    float* out = (float*)d_out;

    transpose_kernel<<<dim3(TT / 32, FFR / 32, BB * CC * 2), dim3(32, 8)>>>(fs, ft);

    gram_kernel<<<144, 256>>>(fs, ft);

    norms_kernel<<<dim3(BB, 2), LTm>>>(0, LTm);
    norms_kernel<<<dim3(BB, 2), LFm>>>(1, LFm);

    rowproc_kernel<<<dim3(LTm, BB, 2), LTm>>>(0, LTm);
    rowproc_kernel<<<dim3(LFm, BB, 2), LFm>>>(1, LFm);

    mlp_kernel<<<dim3(BB, 2), LTm>>>(0, LTm, WqT, bqT, gqT, BqT, WkT, bkT, gkT, BkT);
    mlp_kernel<<<dim3(BB, 2), LFm>>>(1, LFm, WqF, bqF, gqF, BqF, WkF, bkF, gkF, BkF);

    alpha_kernel<<<dim3(LTm, BB), LTm>>>(0, LTm);
    alpha_kernel<<<dim3(LFm, BB), LFm>>>(1, LFm);

    colsum_kernel<<<BB, LTm>>>(0, LTm);
    colsum_kernel<<<BB, LFm>>>(1, LFm);

    part_kernel<<<dim3(LTm / 8, BB), LTm>>>(0, LTm);
    part_kernel<<<dim3(LFm / 8, BB), LFm>>>(1, LFm);

    final_kernel<<<1, 256>>>(out);
}

// round 4
// speedup vs baseline: 1.8864x; 1.8864x over previous
#include <cuda_runtime.h>

#define BB   8
#define CC   64
#define TT   192
#define FFR  128
#define LTm  192               // time view L
#define LFm  128               // freq view L
#define DTm  (CC*FFR)          // 8192
#define DFm  (CC*TT)           // 12288
#define NEL  (BB*CC*TT*FFR)    // 12,582,912
#define HH   4

#define KSEG      1024
#define NSEG_T    (DTm/KSEG)   // 8
#define NSEG_F    (DFm/KSEG)   // 12
#define NBLK_T    (NSEG_T*16*6)  // 768
#define NBLK_F    (NSEG_F*16*3)  // 576
#define NT_E      (16*LTm*LTm)   // 589824
#define NF_E      (16*LFm*LFm)   // 262144

// ---------------- scratch (device globals; no allocations) ----------------
__device__ float g_XT[2][NEL];                  // transposed time-view X for s,t
__device__ float g_GpT[NSEG_T][16][LTm*LTm];    // time partial grams  [seg][which*8+b]
__device__ float g_GpF[NSEG_F][16][LFm*LFm];    // freq partial grams
__device__ float g_G[2][2][BB*LTm*LTm];         // [view][which] gram -> logPs / Pt_row
__device__ float g_inv[2][2][BB*LTm];           // 1/max(norm,eps)
__device__ float g_mean[2][2][BB*LTm];          // row means of P
__device__ float g_ent[2][BB*LTm];              // entropy terms (t side)
__device__ float g_qk[2][2][BB*LTm*HH];         // q (sel=0), k (sel=1)
__device__ float g_alpha[2][BB*LTm*LTm];
__device__ float g_colsum[2][BB*LTm];
__device__ float g_part[2][256];

// ---------------- small helpers ----------------
__device__ __forceinline__ float warpSum(float v) {
#pragma unroll
    for (int o = 16; o; o >>= 1) v += __shfl_xor_sync(0xffffffffu, v, o);
    return v;
}
__device__ __forceinline__ float warpMax(float v) {
#pragma unroll
    for (int o = 16; o; o >>= 1) v = fmaxf(v, __shfl_xor_sync(0xffffffffu, v, o));
    return v;
}
__device__ __forceinline__ float blockSum(float v, float* sm) {
    v = warpSum(v);
    int w = threadIdx.x >> 5;
    __syncthreads();
    if ((threadIdx.x & 31) == 0) sm[w] = v;
    __syncthreads();
    float r = 0.f;
    int nw = (blockDim.x + 31) >> 5;
    for (int i = 0; i < nw; i++) r += sm[i];
    return r;
}
__device__ __forceinline__ float blockMax(float v, float* sm) {
    v = warpMax(v);
    int w = threadIdx.x >> 5;
    __syncthreads();
    if ((threadIdx.x & 31) == 0) sm[w] = v;
    __syncthreads();
    float r = -3.402823466e38f;
    int nw = (blockDim.x + 31) >> 5;
    for (int i = 0; i < nw; i++) r = fmaxf(r, sm[i]);
    return r;
}

union Cvt { unsigned long long u; float2 f; };

__device__ __forceinline__ void lds_v2u64(unsigned long long& x, unsigned long long& y, unsigned addr) {
    asm volatile("ld.shared.v2.u64 {%0,%1}, [%2];" : "=l"(x), "=l"(y) : "r"(addr));
}
__device__ __forceinline__ void fma2(unsigned long long& d, unsigned long long a, unsigned long long b) {
    asm volatile("fma.rn.f32x2 %0, %1, %2, %0;" : "+l"(d) : "l"(a), "l"(b));
}

// ---------------- 1) transpose feat (B,C,T,Fr) -> (B,C,Fr,T), both tensors ----------------
__global__ void transpose_kernel(const float* __restrict__ fs, const float* __restrict__ ft) {
    __shared__ float tile[32][33];
    int z = blockIdx.z;
    int which = z >> 9;            // 0..511 -> fs, 512..1023 -> ft
    int bc = z & 511;
    const float* in = which ? ft : fs;
    int t0 = blockIdx.x * 32, f0 = blockIdx.y * 32;
    const float* src = in + (size_t)bc * TT * FFR;
    float* out = g_XT[which] + (size_t)bc * TT * FFR;
    int tx = threadIdx.x, ty = threadIdx.y;
#pragma unroll
    for (int i = 0; i < 32; i += 8)
        tile[ty + i][tx] = src[(size_t)(t0 + ty + i) * FFR + f0 + tx];
    __syncthreads();
#pragma unroll
    for (int i = 0; i < 32; i += 8)
        out[(size_t)(f0 + ty + i) * TT + t0 + tx] = tile[tx][ty + i];
}

// ---------------- 2) K-split SYRK, FMA-bound micro-kernel ----------------
// 64x64 tile-pair per block, 64 threads, 8x8 per thread, 1024-K segment.
// Both operands stored PLAIN k-major in smem (68-float padded rows); FFMA2
// packed math with register-side duplication of the B operand.
__global__ void __launch_bounds__(64) gram2_kernel(const float* __restrict__ fs,
                                                   const float* __restrict__ ft) {
    int bid = blockIdx.x;
    int view, seg, bw, pair, nt, L;
    if (bid < NBLK_T) { view = 0; seg = bid / 96; int r = bid % 96; bw = r / 6; pair = r % 6; nt = 3; L = LTm; }
    else { int b2 = bid - NBLK_T; view = 1; seg = b2 / 48; int r = b2 % 48; bw = r / 3; pair = r % 3; nt = 2; L = LFm; }

    int pi = 0, rem = pair, rl = nt;
    while (rem >= rl) { rem -= rl; pi++; rl--; }
    int pj = pi + rem;
    int i0 = pi * 64, j0 = pj * 64;
    int which = bw >> 3, b = bw & 7;

    const float* X = (view == 0) ? g_XT[which] : (which ? ft : fs);
    int D = (view == 0) ? DTm : DFm;
    X += (size_t)b * L * D + (size_t)(seg * KSEG) * L;

    __shared__ __align__(16) float sA[32 * 68];
    __shared__ __align__(16) float sB[32 * 68];

    int tid = threadIdx.x;
    int rq = tid & 15, lkh = tid >> 4;     // loader mapping
    int tx = tid & 7, ty = tid >> 3;       // compute mapping

    float4 ga[8], gb[8];
#pragma unroll
    for (int m = 0; m < 8; m++) {
        int kk = lkh * 8 + ((m + 2 * rq) & 7);
        ga[m] = *(const float4*)&X[(size_t)kk * L + i0 + rq * 4];
        gb[m] = *(const float4*)&X[(size_t)kk * L + j0 + rq * 4];
    }

    unsigned long long acc[4][8];
#pragma unroll
    for (int rp = 0; rp < 4; rp++)
#pragma unroll
        for (int j = 0; j < 8; j++) acc[rp][j] = 0ull;

    unsigned sAb = (unsigned)__cvta_generic_to_shared(sA);
    unsigned sBb = (unsigned)__cvta_generic_to_shared(sB);
    unsigned aAddr = sAb + (unsigned)ty * 32;
    unsigned bAddr = sBb + (unsigned)tx * 32;

    for (int ch = 0; ; ch++) {
        __syncthreads();
#pragma unroll
        for (int m = 0; m < 8; m++) {
            int kk = lkh * 8 + ((m + 2 * rq) & 7);
            *(float4*)&sA[kk * 68 + rq * 4] = ga[m];
            *(float4*)&sB[kk * 68 + rq * 4] = gb[m];
        }
        __syncthreads();
        bool more = (ch + 1 < 32);
        if (more) {
            const float* Xn = X + (size_t)(ch + 1) * 32 * L;
#pragma unroll
            for (int m = 0; m < 8; m++) {
                int kk = lkh * 8 + ((m + 2 * rq) & 7);
                ga[m] = *(const float4*)&Xn[(size_t)kk * L + i0 + rq * 4];
                gb[m] = *(const float4*)&Xn[(size_t)kk * L + j0 + rq * 4];
            }
        }
#pragma unroll
        for (int kk = 0; kk < 32; kk++) {
            unsigned long long a01, a23, a45, a67, b01, b23, b45, b67;
            lds_v2u64(a01, a23, aAddr + kk * 272);
            lds_v2u64(a45, a67, aAddr + kk * 272 + 16);
            lds_v2u64(b01, b23, bAddr + kk * 272);
            lds_v2u64(b45, b67, bAddr + kk * 272 + 16);
            float bv[8];
            { Cvt c; c.u = b01; bv[0] = c.f.x; bv[1] = c.f.y; }
            { Cvt c; c.u = b23; bv[2] = c.f.x; bv[3] = c.f.y; }
            { Cvt c; c.u = b45; bv[4] = c.f.x; bv[5] = c.f.y; }
            { Cvt c; c.u = b67; bv[6] = c.f.x; bv[7] = c.f.y; }
#pragma unroll
            for (int j = 0; j < 8; j++) {
                Cvt d; d.f.x = bv[j]; d.f.y = bv[j];
                unsigned long long bd = d.u;
                fma2(acc[0][j], a01, bd);
                fma2(acc[1][j], a23, bd);
                fma2(acc[2][j], a45, bd);
                fma2(acc[3][j], a67, bd);
            }
        }
        if (!more) break;
    }

    float* Gp = (view == 0) ? &g_GpT[seg][bw][0] : &g_GpF[seg][bw][0];
#pragma unroll
    for (int rp = 0; rp < 4; rp++) {
        float lo[8], hi[8];
#pragma unroll
        for (int j = 0; j < 8; j++) { Cvt c; c.u = acc[rp][j]; lo[j] = c.f.x; hi[j] = c.f.y; }
        int r0 = i0 + ty * 8 + rp * 2;
        float4* p0 = (float4*)&Gp[(size_t)r0 * L + j0 + tx * 8];
        p0[0] = make_float4(lo[0], lo[1], lo[2], lo[3]);
        p0[1] = make_float4(lo[4], lo[5], lo[6], lo[7]);
        float4* p1 = (float4*)&Gp[(size_t)(r0 + 1) * L + j0 + tx * 8];
        p1[0] = make_float4(hi[0], hi[1], hi[2], hi[3]);
        p1[1] = make_float4(hi[4], hi[5], hi[6], hi[7]);
    }
}

// ---------------- 3) sum partials + mirror + fused norms ----------------
__global__ void sumG_kernel() {
    int idx = blockIdx.x * 256 + threadIdx.x;
    if (idx < NT_E) {
        int bw = idx / (LTm * LTm), e = idx % (LTm * LTm);
        int i = e / LTm, j = e % LTm;
        int es = ((i >> 6) <= (j >> 6)) ? e : j * LTm + i;
        float s = 0.f;
#pragma unroll
        for (int g = 0; g < NSEG_T; g++) s += g_GpT[g][bw][es];
        int which = bw >> 3, b = bw & 7;
        g_G[0][which][(size_t)b * LTm * LTm + e] = s;
        if (i == j) g_inv[0][which][b * LTm + i] = 1.0f / fmaxf(sqrtf(s), 1e-8f);
    } else {
        idx -= NT_E;
        int bw = idx / (LFm * LFm), e = idx % (LFm * LFm);
        int i = e / LFm, j = e % LFm;
        int es = ((i >> 6) <= (j >> 6)) ? e : j * LFm + i;
        float s = 0.f;
#pragma unroll
        for (int g = 0; g < NSEG_F; g++) s += g_GpF[g][bw][es];
        int which = bw >> 3, b = bw & 7;
        g_G[1][which][(size_t)b * LFm * LFm + e] = s;
        if (i == j) g_inv[1][which][b * LFm + i] = 1.0f / fmaxf(sqrtf(s), 1e-8f);
    }
}

// ---------------- 4) per-row: P, rowmean, softmax(+eps), log / entropy (in place) ----------------
__global__ void rowproc_kernel(int view, int L) {
    __shared__ float red[8];
    int l = blockIdx.x, b = blockIdx.y, which = blockIdx.z;
    int m = threadIdx.x;
    float* G = g_G[view][which] + (size_t)b * L * L + (size_t)l * L;
    float invl = g_inv[view][which][b * L + l];
    float invm = g_inv[view][which][b * L + m];
    float pv = 0.5f * (G[m] * invl * invm + 1.0f);

    float s = blockSum(pv, red);
    if (m == 0) g_mean[view][which][b * L + l] = s / (float)L;

    float mx = blockMax(pv, red);
    float e = expf(pv - mx);
    float Z = blockSum(e, red);
    float sp = e / Z + 1e-8f;                    // P_row = softmax + EPS

    if (which == 0) {
        G[m] = logf(sp + 1e-8f);                 // logPs = log(P_row + EPS)
    } else {
        G[m] = sp;                               // Pt_row
        float ent = blockSum(sp * logf(sp + 1e-8f), red);
        if (m == 0) g_ent[view][b * L + l] = ent;
    }
}

// ---------------- 5) tiny MLP (Linear(1,H)+ReLU+LayerNorm) ----------------
__global__ void mlp_kernel(int view, int L,
                           const float* __restrict__ Wq, const float* __restrict__ bq,
                           const float* __restrict__ gq, const float* __restrict__ Bq,
                           const float* __restrict__ Wk, const float* __restrict__ bk,
                           const float* __restrict__ gk, const float* __restrict__ Bk) {
    int b = blockIdx.x, sel = blockIdx.y;
    int l = threadIdx.x;
    const float* W  = sel ? Wk : Wq;
    const float* bi = sel ? bk : bq;
    const float* gg = sel ? gk : gq;
    const float* be = sel ? Bk : Bq;
    float x = g_mean[view][sel][b * L + l];
    float h[HH]; float mu = 0.f;
#pragma unroll
    for (int j = 0; j < HH; j++) { h[j] = fmaxf(W[j] * x + bi[j], 0.f); mu += h[j]; }
    mu *= (1.0f / HH);
    float var = 0.f;
#pragma unroll
    for (int j = 0; j < HH; j++) { float d = h[j] - mu; var += d * d; }
    var *= (1.0f / HH);
    float inv = rsqrtf(var + 1e-5f);
#pragma unroll
    for (int j = 0; j < HH; j++)
        g_qk[view][sel][((size_t)b * L + l) * HH + j] = gg[j] * (h[j] - mu) * inv + be[j];
}

// ---------------- 6) alpha = softmax(q k^T / sqrt(H+eps)) ----------------
__global__ void alpha_kernel(int view, int L) {
    __shared__ float kb[LTm * HH];
    __shared__ float red[8];
    int s = blockIdx.x, b = blockIdx.y;
    int t = threadIdx.x;
    for (int i = t; i < L * HH; i += blockDim.x)
        kb[i] = g_qk[view][1][(size_t)b * L * HH + i];
    float q0 = g_qk[view][0][((size_t)b * L + s) * HH + 0];
    float q1 = g_qk[view][0][((size_t)b * L + s) * HH + 1];
    float q2 = g_qk[view][0][((size_t)b * L + s) * HH + 2];
    float q3 = g_qk[view][0][((size_t)b * L + s) * HH + 3];
    __syncthreads();
    float invScale = rsqrtf(4.0f + 1e-8f);
    float a = (q0 * kb[t * 4 + 0] + q1 * kb[t * 4 + 1] + q2 * kb[t * 4 + 2] + q3 * kb[t * 4 + 3]) * invScale;
    float mx = blockMax(a, red);
    float e = expf(a - mx);
    float Z = blockSum(e, red);
    g_alpha[view][(size_t)b * L * L + (size_t)s * L + t] = e / Z;
}

// ---------------- 7) column sums of alpha ----------------
__global__ void colsum_kernel(int view, int L) {
    int b = blockIdx.x, t = threadIdx.x;
    const float* al = g_alpha[view] + (size_t)b * L * L;
    float s = 0.f;
    for (int ss = 0; ss < L; ss++) s += al[(size_t)ss * L + t];
    g_colsum[view][b * L + t] = s;
}

// ---------------- 8) term2 partials ----------------
__global__ void part_kernel(int view, int L) {
    __shared__ float sal[8][LTm];
    __shared__ float red[8];
    int b = blockIdx.y, s0 = blockIdx.x * 8;
    const float* logPs = g_G[view][0] + (size_t)b * L * L;
    const float* Pt    = g_G[view][1] + (size_t)b * L * L;
    const float* al    = g_alpha[view] + (size_t)b * L * L;
    int k = threadIdx.x;
#pragma unroll
    for (int i = 0; i < 8; i++) sal[i][k] = al[(size_t)(s0 + i) * L + k];
    __syncthreads();
    float m[8];
#pragma unroll
    for (int i = 0; i < 8; i++) m[i] = 0.f;
    for (int t = 0; t < L; t++) {
        float pv = Pt[(size_t)t * L + k];
#pragma unroll
        for (int i = 0; i < 8; i++) m[i] += sal[i][t] * pv;
    }
    float acc = 0.f;
#pragma unroll
    for (int i = 0; i < 8; i++) acc += m[i] * logPs[(size_t)(s0 + i) * L + k];
    float tot = blockSum(acc, red);
    if (k == 0) g_part[view][blockIdx.y * gridDim.x + blockIdx.x] = tot;
}

// ---------------- 9) final deterministic reduction ----------------
__global__ void final_kernel(float* out) {
    __shared__ float red[8];
    int tid = threadIdx.x;
    float t2T = 0.f; for (int i = tid; i < (LTm / 8) * BB; i += 256) t2T += g_part[0][i];
    t2T = blockSum(t2T, red);
    float t2F = 0.f; for (int i = tid; i < (LFm / 8) * BB; i += 256) t2F += g_part[1][i];
    t2F = blockSum(t2F, red);
    float t1T = 0.f; for (int i = tid; i < BB * LTm; i += 256) t1T += g_ent[0][i] * g_colsum[0][i];
    t1T = blockSum(t1T, red);
    float t1F = 0.f; for (int i = tid; i < BB * LFm; i += 256) t1F += g_ent[1][i] * g_colsum[1][i];
    t1F = blockSum(t1F, red);
    if (tid == 0) {
        float lt = (t1T - t2T) / ((float)BB * LTm * LTm + 1e-8f);
        float lf = (t1F - t2F) / ((float)BB * LFm * LFm + 1e-8f);
        out[0] = lt + lf;
    }
}

// ---------------- launch ----------------
extern "C" void kernel_launch(void* const* d_in, const int* in_sizes, int n_in,
                              void* d_out, int out_size) {
    const float* fs  = (const float*)d_in[0];
    const float* ft  = (const float*)d_in[1];
    const float* WqT = (const float*)d_in[2];
    const float* bqT = (const float*)d_in[3];
    const float* gqT = (const float*)d_in[4];
    const float* BqT = (const float*)d_in[5];
    const float* WkT = (const float*)d_in[6];
    const float* bkT = (const float*)d_in[7];
    const float* gkT = (const float*)d_in[8];
    const float* BkT = (const float*)d_in[9];
    const float* WqF = (const float*)d_in[10];
    const float* bqF = (const float*)d_in[11];
    const float* gqF = (const float*)d_in[12];
    const float* BqF = (const float*)d_in[13];
    const float* WkF = (const float*)d_in[14];
    const float* bkF = (const float*)d_in[15];
    const float* gkF = (const float*)d_in[16];
    const float* BkF = (const float*)d_in[17];
    float* out = (float*)d_out;

    transpose_kernel<<<dim3(TT / 32, FFR / 32, BB * CC * 2), dim3(32, 8)>>>(fs, ft);

    gram2_kernel<<<NBLK_T + NBLK_F, 64>>>(fs, ft);

    sumG_kernel<<<(NT_E + NF_E) / 256, 256>>>();

    rowproc_kernel<<<dim3(LTm, BB, 2), LTm>>>(0, LTm);
    rowproc_kernel<<<dim3(LFm, BB, 2), LFm>>>(1, LFm);

    mlp_kernel<<<dim3(BB, 2), LTm>>>(0, LTm, WqT, bqT, gqT, BqT, WkT, bkT, gkT, BkT);
    mlp_kernel<<<dim3(BB, 2), LFm>>>(1, LFm, WqF, bqF, gqF, BqF, WkF, bkF, gkF, BkF);

    alpha_kernel<<<dim3(LTm, BB), LTm>>>(0, LTm);
    alpha_kernel<<<dim3(LFm, BB), LFm>>>(1, LFm);

    colsum_kernel<<<BB, LTm>>>(0, LTm);
    colsum_kernel<<<BB, LFm>>>(1, LFm);

    part_kernel<<<dim3(LTm / 8, BB), LTm>>>(0, LTm);
    part_kernel<<<dim3(LFm / 8, BB), LFm>>>(1, LFm);

    final_kernel<<<1, 256>>>(out);
}

// round 6
// speedup vs baseline: 2.8343x; 1.5025x over previous
#include <cuda_runtime.h>

#define BB   8
#define CC   64
#define TT   192
#define FFR  128
#define LTm  192               // time view L
#define LFm  128               // freq view L
#define DTm  (CC*FFR)          // 8192
#define DFm  (CC*TT)           // 12288
#define NEL  (BB*CC*TT*FFR)    // 12,582,912
#define HH   4

#define SEGS_T  8
#define SEGS_F  12
#define NBLK_T  (SEGS_T*16)    // 128
#define NBLK_F  (SEGS_F*16)    // 192
#define NT_E    (16*LTm*LTm)   // 589824
#define NF_E    (16*LFm*LFm)   // 262144

// ---------------- scratch (device globals; no allocations) ----------------
__device__ float g_XT[2][NEL];                  // transposed (B,C,Fr,T) fp32 for freq view
__device__ float g_GpT[SEGS_T][16][LTm*LTm];    // time partial grams [seg][which*8+b]
__device__ float g_GpF[SEGS_F][16][LFm*LFm];    // freq partial grams
__device__ float g_G[2][2][BB*LTm*LTm];         // [view][which] gram -> logPs / Pt_row
__device__ float g_inv[2][2][BB*LTm];
__device__ float g_mean[2][2][BB*LTm];
__device__ float g_ent[2][BB*LTm];
__device__ float g_qk[2][2][BB*LTm*HH];
__device__ float g_alpha[2][BB*LTm*LTm];
__device__ float g_colsum[2][BB*LTm];
__device__ float g_part[2][256];

// ---------------- small helpers ----------------
__device__ __forceinline__ float warpSum(float v) {
#pragma unroll
    for (int o = 16; o; o >>= 1) v += __shfl_xor_sync(0xffffffffu, v, o);
    return v;
}
__device__ __forceinline__ float warpMax(float v) {
#pragma unroll
    for (int o = 16; o; o >>= 1) v = fmaxf(v, __shfl_xor_sync(0xffffffffu, v, o));
    return v;
}
__device__ __forceinline__ float blockSum(float v, float* sm) {
    v = warpSum(v);
    int w = threadIdx.x >> 5;
    __syncthreads();
    if ((threadIdx.x & 31) == 0) sm[w] = v;
    __syncthreads();
    float r = 0.f;
    int nw = (blockDim.x + 31) >> 5;
    for (int i = 0; i < nw; i++) r += sm[i];
    return r;
}
__device__ __forceinline__ float blockMax(float v, float* sm) {
    v = warpMax(v);
    int w = threadIdx.x >> 5;
    __syncthreads();
    if ((threadIdx.x & 31) == 0) sm[w] = v;
    __syncthreads();
    float r = -3.402823466e38f;
    int nw = (blockDim.x + 31) >> 5;
    for (int i = 0; i < nw; i++) r = fmaxf(r, sm[i]);
    return r;
}

// ---------------- mma.sync helpers (baseline PTX; no tcgen05) ----------------
__device__ __forceinline__ unsigned packbf(float hi, float lo) {   // hi->upper16, lo->lower16
    unsigned r;
    asm("cvt.rn.bf16x2.f32 %0, %1, %2;" : "=r"(r) : "f"(hi), "f"(lo));
    return r;
}
__device__ __forceinline__ void sts64(unsigned a, unsigned w0, unsigned w1) {
    asm volatile("st.shared.v2.b32 [%0], {%1,%2};" :: "r"(a), "r"(w0), "r"(w1) : "memory");
}
__device__ __forceinline__ void ldsm4(unsigned* r, unsigned a) {
    asm volatile("ldmatrix.sync.aligned.m8n8.x4.shared.b16 {%0,%1,%2,%3}, [%4];"
                 : "=r"(r[0]), "=r"(r[1]), "=r"(r[2]), "=r"(r[3]) : "r"(a));
}
__device__ __forceinline__ void mma16816(float* d, const unsigned* a, unsigned b0, unsigned b1) {
    asm volatile("mma.sync.aligned.m16n8k16.row.col.f32.bf16.bf16.f32 "
                 "{%0,%1,%2,%3}, {%4,%5,%6,%7}, {%8,%9}, {%0,%1,%2,%3};"
                 : "+f"(d[0]), "+f"(d[1]), "+f"(d[2]), "+f"(d[3])
                 : "r"(a[0]), "r"(a[1]), "r"(a[2]), "r"(a[3]), "r"(b0), "r"(b1));
}
// swizzled smem address: 64B rows, 16B chunk XOR (row>>1)&3  -> conflict-free ldmatrix
__device__ __forceinline__ unsigned swa(unsigned base, int row, int kbyte) {
    return base + row * 64 + (((((unsigned)kbyte >> 4) ^ (((unsigned)row >> 1) & 3u)) & 3u) << 4);
}

// ---------------- 1) transpose feat (B,C,T,Fr) -> (B,C,Fr,T), both tensors ----------------
__global__ void transpose_kernel(const float* __restrict__ fs, const float* __restrict__ ft) {
    __shared__ float tile[32][33];
    int z = blockIdx.z;
    int which = z >> 9;
    int bc = z & 511;
    const float* in = which ? ft : fs;
    int t0 = blockIdx.x * 32, f0 = blockIdx.y * 32;
    const float* src = in + (size_t)bc * TT * FFR;
    float* out = g_XT[which] + (size_t)bc * TT * FFR;
    int tx = threadIdx.x, ty = threadIdx.y;
#pragma unroll
    for (int i = 0; i < 32; i += 8)
        tile[ty + i][tx] = src[(size_t)(t0 + ty + i) * FFR + f0 + tx];
    __syncthreads();
#pragma unroll
    for (int i = 0; i < 32; i += 8)
        out[(size_t)(f0 + ty + i) * TT + t0 + tx] = tile[tx][ty + i];
}

// ---------------- 2) bf16-split SYRK via mma.sync (tensor pipe, sm_80 path) ----------------
// Per CTA: (view, which, b, 1024-K seg). K-chunks of 32: fill hi/lo bf16 smem
// tiles (swizzled), 3 accumulating MMAs (HH, HL, LH) per kstep, fp32 acc regs.
template<int L, int MI, int NP, int NPF>
__device__ __forceinline__ void gram_body(
    const float* __restrict__ src, int rstride, int cdiv, int cstride,
    int seg, float* __restrict__ Gp, unsigned hb, unsigned lb, int m0w, int j0w)
{
    int tid = threadIdx.x, lane = tid & 31;
    int t8 = lane >> 3, r8 = lane & 7;
    int aro = r8 + (t8 & 1) * 8, ako = (t8 >> 1) * 16;   // A-fragment lane offsets
    int bro = r8 + (t8 >> 1) * 8, bko = (t8 & 1) * 16;   // B-fragment lane offsets

    float acc[MI][2 * NP][4];
#pragma unroll
    for (int mi = 0; mi < MI; mi++)
#pragma unroll
        for (int n = 0; n < 2 * NP; n++)
#pragma unroll
            for (int u = 0; u < 4; u++) acc[mi][n][u] = 0.f;

    float4 pf[NPF];
    {
        int k0 = seg * 1024;
        int c = k0 / cdiv;
        const float* cb = src + (size_t)c * cstride + (k0 - c * cdiv);
#pragma unroll
        for (int i = 0; i < NPF; i++) {
            int lin = i * 256 + tid, r = lin >> 3, q = lin & 7;
            pf[i] = *(const float4*)(cb + (size_t)r * rstride + q * 4);
        }
    }

    for (int ch = 0; ch < 32; ch++) {
        // convert + store hi/lo bf16 tiles
#pragma unroll
        for (int i = 0; i < NPF; i++) {
            int lin = i * 256 + tid, r = lin >> 3, q = lin & 7;
            float4 v = pf[i];
            unsigned h0 = packbf(v.y, v.x);
            unsigned h1 = packbf(v.w, v.z);
            float a0 = __uint_as_float(h0 << 16);
            float a1 = __uint_as_float(h0 & 0xffff0000u);
            float a2 = __uint_as_float(h1 << 16);
            float a3 = __uint_as_float(h1 & 0xffff0000u);
            unsigned l0 = packbf(v.y - a1, v.x - a0);
            unsigned l1 = packbf(v.w - a3, v.z - a2);
            unsigned off = (unsigned)(r * 64) + (((((unsigned)q >> 1) ^ (((unsigned)r >> 1) & 3u)) & 3u) << 4) + (((unsigned)q & 1u) << 3);
            sts64(hb + off, h0, h1);
            sts64(lb + off, l0, l1);
        }
        __syncthreads();

        if (ch < 31) {
            int k0 = seg * 1024 + (ch + 1) * 32;
            int c = k0 / cdiv;
            const float* cb = src + (size_t)c * cstride + (k0 - c * cdiv);
#pragma unroll
            for (int i = 0; i < NPF; i++) {
                int lin = i * 256 + tid, r = lin >> 3, q = lin & 7;
                pf[i] = *(const float4*)(cb + (size_t)r * rstride + q * 4);
            }
        }

#pragma unroll
        for (int ks = 0; ks < 2; ks++) {
            int kb = ks * 32;
            unsigned ah[MI][4], bh[NP][4];
#pragma unroll
            for (int mi = 0; mi < MI; mi++) ldsm4(ah[mi], swa(hb, m0w + mi * 16 + aro, kb + ako));
#pragma unroll
            for (int nj = 0; nj < NP; nj++) ldsm4(bh[nj], swa(hb, j0w + nj * 16 + bro, kb + bko));
#pragma unroll
            for (int mi = 0; mi < MI; mi++)
#pragma unroll
                for (int nj = 0; nj < NP; nj++) {
                    mma16816(acc[mi][2 * nj],     ah[mi], bh[nj][0], bh[nj][1]);
                    mma16816(acc[mi][2 * nj + 1], ah[mi], bh[nj][2], bh[nj][3]);
                }
            unsigned bl[NP][4];
#pragma unroll
            for (int nj = 0; nj < NP; nj++) ldsm4(bl[nj], swa(lb, j0w + nj * 16 + bro, kb + bko));
#pragma unroll
            for (int mi = 0; mi < MI; mi++)
#pragma unroll
                for (int nj = 0; nj < NP; nj++) {
                    mma16816(acc[mi][2 * nj],     ah[mi], bl[nj][0], bl[nj][1]);
                    mma16816(acc[mi][2 * nj + 1], ah[mi], bl[nj][2], bl[nj][3]);
                }
            unsigned al[MI][4];
#pragma unroll
            for (int mi = 0; mi < MI; mi++) ldsm4(al[mi], swa(lb, m0w + mi * 16 + aro, kb + ako));
#pragma unroll
            for (int mi = 0; mi < MI; mi++)
#pragma unroll
                for (int nj = 0; nj < NP; nj++) {
                    mma16816(acc[mi][2 * nj],     al[mi], bh[nj][0], bh[nj][1]);
                    mma16816(acc[mi][2 * nj + 1], al[mi], bh[nj][2], bh[nj][3]);
                }
        }
        __syncthreads();
    }

    // writeout (c-frag: rows lane/4, lane/4+8; cols (lane%4)*2)
    int rq = lane >> 2, cq = lane & 3;
#pragma unroll
    for (int mi = 0; mi < MI; mi++)
#pragma unroll
        for (int n = 0; n < 2 * NP; n++) {
            int m = m0w + mi * 16 + rq, j = j0w + n * 8 + cq * 2;
            *(float2*)&Gp[(size_t)m * L + j] = make_float2(acc[mi][n][0], acc[mi][n][1]);
            *(float2*)&Gp[(size_t)(m + 8) * L + j] = make_float2(acc[mi][n][2], acc[mi][n][3]);
        }
}

__global__ void __launch_bounds__(256, 1) gram_kernel(const float* __restrict__ fs,
                                                      const float* __restrict__ ft) {
    extern __shared__ __align__(16) char smraw[];
    unsigned sb = (unsigned)__cvta_generic_to_shared(smraw);
    int wid = threadIdx.x >> 5;
    int bid = blockIdx.x;

    if (bid < NBLK_T) {
        int seg = bid >> 4, bw = bid & 15;
        int which = bw >> 3, b = bw & 7;
        const float* src = (which ? ft : fs) + (size_t)b * CC * TT * FFR;
        float* Gp = &g_GpT[seg][bw][0];
        int m0w = (wid >> 2) * 96, j0w = (wid & 3) * 48;
        gram_body<LTm, 6, 3, 6>(src, FFR, 128, TT * FFR, seg, Gp,
                                sb, sb + LTm * 64, m0w, j0w);
    } else {
        int r = bid - NBLK_T;
        int seg = r >> 4, bw = r & 15;
        int which = bw >> 3, b = bw & 7;
        const float* src = g_XT[which] + (size_t)b * CC * FFR * TT;
        float* Gp = &g_GpF[seg][bw][0];
        int m0w = (wid & 3) * 32, j0w = (wid >> 2) * 64;
        gram_body<LFm, 2, 4, 4>(src, TT, 192, FFR * TT, seg, Gp,
                                sb, sb + LFm * 64, m0w, j0w);
    }
}

// ---------------- 3) sum partials + fused norms (full matrices; no mirror) ----------------
__global__ void sumG_kernel() {
    int idx = blockIdx.x * 256 + threadIdx.x;
    if (idx < NT_E) {
        int bw = idx / (LTm * LTm), e = idx % (LTm * LTm);
        int i = e / LTm, j = e % LTm;
        float s = 0.f;
#pragma unroll
        for (int g = 0; g < SEGS_T; g++) s += g_GpT[g][bw][e];
        int which = bw >> 3, b = bw & 7;
        g_G[0][which][(size_t)b * LTm * LTm + e] = s;
        if (i == j) g_inv[0][which][b * LTm + i] = 1.0f / fmaxf(sqrtf(s), 1e-8f);
    } else {
        idx -= NT_E;
        int bw = idx / (LFm * LFm), e = idx % (LFm * LFm);
        int i = e / LFm, j = e % LFm;
        float s = 0.f;
#pragma unroll
        for (int g = 0; g < SEGS_F; g++) s += g_GpF[g][bw][e];
        int which = bw >> 3, b = bw & 7;
        g_G[1][which][(size_t)b * LFm * LFm + e] = s;
        if (i == j) g_inv[1][which][b * LFm + i] = 1.0f / fmaxf(sqrtf(s), 1e-8f);
    }
}

// ---------------- 4) per-row: P, rowmean, softmax(+eps), log / entropy ----------------
__global__ void rowproc_kernel(int view, int L) {
    __shared__ float red[8];
    int l = blockIdx.x, b = blockIdx.y, which = blockIdx.z;
    int m = threadIdx.x;
    float* G = g_G[view][which] + (size_t)b * L * L + (size_t)l * L;
    float invl = g_inv[view][which][b * L + l];
    float invm = g_inv[view][which][b * L + m];
    float pv = 0.5f * (G[m] * invl * invm + 1.0f);

    float s = blockSum(pv, red);
    if (m == 0) g_mean[view][which][b * L + l] = s / (float)L;

    float mx = blockMax(pv, red);
    float e = expf(pv - mx);
    float Z = blockSum(e, red);
    float sp = e / Z + 1e-8f;

    if (which == 0) {
        G[m] = logf(sp + 1e-8f);
    } else {
        G[m] = sp;
        float ent = blockSum(sp * logf(sp + 1e-8f), red);
        if (m == 0) g_ent[view][b * L + l] = ent;
    }
}

// ---------------- 5) tiny MLP ----------------
__global__ void mlp_kernel(int view, int L,
                           const float* __restrict__ Wq, const float* __restrict__ bq,
                           const float* __restrict__ gq, const float* __restrict__ Bq,
                           const float* __restrict__ Wk, const float* __restrict__ bk,
                           const float* __restrict__ gk, const float* __restrict__ Bk) {
    int b = blockIdx.x, sel = blockIdx.y;
    int l = threadIdx.x;
    const float* W  = sel ? Wk : Wq;
    const float* bi = sel ? bk : bq;
    const float* gg = sel ? gk : gq;
    const float* be = sel ? Bk : Bq;
    float x = g_mean[view][sel][b * L + l];
    float h[HH]; float mu = 0.f;
#pragma unroll
    for (int j = 0; j < HH; j++) { h[j] = fmaxf(W[j] * x + bi[j], 0.f); mu += h[j]; }
    mu *= (1.0f / HH);
    float var = 0.f;
#pragma unroll
    for (int j = 0; j < HH; j++) { float d = h[j] - mu; var += d * d; }
    var *= (1.0f / HH);
    float inv = rsqrtf(var + 1e-5f);
#pragma unroll
    for (int j = 0; j < HH; j++)
        g_qk[view][sel][((size_t)b * L + l) * HH + j] = gg[j] * (h[j] - mu) * inv + be[j];
}

// ---------------- 6) alpha ----------------
__global__ void alpha_kernel(int view, int L) {
    __shared__ float kb[LTm * HH];
    __shared__ float red[8];
    int s = blockIdx.x, b = blockIdx.y;
    int t = threadIdx.x;
    for (int i = t; i < L * HH; i += blockDim.x)
        kb[i] = g_qk[view][1][(size_t)b * L * HH + i];
    float q0 = g_qk[view][0][((size_t)b * L + s) * HH + 0];
    float q1 = g_qk[view][0][((size_t)b * L + s) * HH + 1];
    float q2 = g_qk[view][0][((size_t)b * L + s) * HH + 2];
    float q3 = g_qk[view][0][((size_t)b * L + s) * HH + 3];
    __syncthreads();
    float invScale = rsqrtf(4.0f + 1e-8f);
    float a = (q0 * kb[t * 4 + 0] + q1 * kb[t * 4 + 1] + q2 * kb[t * 4 + 2] + q3 * kb[t * 4 + 3]) * invScale;
    float mx = blockMax(a, red);
    float e = expf(a - mx);
    float Z = blockSum(e, red);
    g_alpha[view][(size_t)b * L * L + (size_t)s * L + t] = e / Z;
}

// ---------------- 7) column sums of alpha ----------------
__global__ void colsum_kernel(int view, int L) {
    int b = blockIdx.x, t = threadIdx.x;
    const float* al = g_alpha[view] + (size_t)b * L * L;
    float s = 0.f;
    for (int ss = 0; ss < L; ss++) s += al[(size_t)ss * L + t];
    g_colsum[view][b * L + t] = s;
}

// ---------------- 8) term2 partials ----------------
__global__ void part_kernel(int view, int L) {
    __shared__ float sal[8][LTm];
    __shared__ float red[8];
    int b = blockIdx.y, s0 = blockIdx.x * 8;
    const float* logPs = g_G[view][0] + (size_t)b * L * L;
    const float* Pt    = g_G[view][1] + (size_t)b * L * L;
    const float* al    = g_alpha[view] + (size_t)b * L * L;
    int k = threadIdx.x;
#pragma unroll
    for (int i = 0; i < 8; i++) sal[i][k] = al[(size_t)(s0 + i) * L + k];
    __syncthreads();
    float m[8];
#pragma unroll
    for (int i = 0; i < 8; i++) m[i] = 0.f;
    for (int t = 0; t < L; t++) {
        float pv = Pt[(size_t)t * L + k];
#pragma unroll
        for (int i = 0; i < 8; i++) m[i] += sal[i][t] * pv;
    }
    float acc = 0.f;
#pragma unroll
    for (int i = 0; i < 8; i++) acc += m[i] * logPs[(size_t)(s0 + i) * L + k];
    float tot = blockSum(acc, red);
    if (k == 0) g_part[view][blockIdx.y * gridDim.x + blockIdx.x] = tot;
}

// ---------------- 9) final deterministic reduction ----------------
__global__ void final_kernel(float* out) {
    __shared__ float red[8];
    int tid = threadIdx.x;
    float t2T = 0.f; for (int i = tid; i < (LTm / 8) * BB; i += 256) t2T += g_part[0][i];
    t2T = blockSum(t2T, red);
    float t2F = 0.f; for (int i = tid; i < (LFm / 8) * BB; i += 256) t2F += g_part[1][i];
    t2F = blockSum(t2F, red);
    float t1T = 0.f; for (int i = tid; i < BB * LTm; i += 256) t1T += g_ent[0][i] * g_colsum[0][i];
    t1T = blockSum(t1T, red);
    float t1F = 0.f; for (int i = tid; i < BB * LFm; i += 256) t1F += g_ent[1][i] * g_colsum[1][i];
    t1F = blockSum(t1F, red);
    if (tid == 0) {
        float lt = (t1T - t2T) / ((float)BB * LTm * LTm + 1e-8f);
        float lf = (t1F - t2F) / ((float)BB * LFm * LFm + 1e-8f);
        out[0] = lt + lf;
    }
}

// ---------------- launch ----------------
extern "C" void kernel_launch(void* const* d_in, const int* in_sizes, int n_in,
                              void* d_out, int out_size) {
    const float* fs  = (const float*)d_in[0];
    const float* ft  = (const float*)d_in[1];
    const float* WqT = (const float*)d_in[2];
    const float* bqT = (const float*)d_in[3];
    const float* gqT = (const float*)d_in[4];
    const float* BqT = (const float*)d_in[5];
    const float* WkT = (const float*)d_in[6];
    const float* bkT = (const float*)d_in[7];
    const float* gkT = (const float*)d_in[8];
    const float* BkT = (const float*)d_in[9];
    const float* WqF = (const float*)d_in[10];
    const float* bqF = (const float*)d_in[11];
    const float* gqF = (const float*)d_in[12];
    const float* BqF = (const float*)d_in[13];
    const float* WkF = (const float*)d_in[14];
    const float* bkF = (const float*)d_in[15];
    const float* gkF = (const float*)d_in[16];
    const float* BkF = (const float*)d_in[17];
    float* out = (float*)d_out;

    transpose_kernel<<<dim3(TT / 32, FFR / 32, BB * CC * 2), dim3(32, 8)>>>(fs, ft);

    gram_kernel<<<NBLK_T + NBLK_F, 256, 2 * LTm * 64>>>(fs, ft);

    sumG_kernel<<<(NT_E + NF_E) / 256, 256>>>();

    rowproc_kernel<<<dim3(LTm, BB, 2), LTm>>>(0, LTm);
    rowproc_kernel<<<dim3(LFm, BB, 2), LFm>>>(1, LFm);

    mlp_kernel<<<dim3(BB, 2), LTm>>>(0, LTm, WqT, bqT, gqT, BqT, WkT, bkT, gkT, BkT);
    mlp_kernel<<<dim3(BB, 2), LFm>>>(1, LFm, WqF, bqF, gqF, BqF, WkF, bkF, gkF, BkF);

    alpha_kernel<<<dim3(LTm, BB), LTm>>>(0, LTm);
    alpha_kernel<<<dim3(LFm, BB), LFm>>>(1, LFm);

    colsum_kernel<<<BB, LTm>>>(0, LTm);
    colsum_kernel<<<BB, LFm>>>(1, LFm);

    part_kernel<<<dim3(LTm / 8, BB), LTm>>>(0, LTm);
    part_kernel<<<dim3(LFm / 8, BB), LFm>>>(1, LFm);

    final_kernel<<<1, 256>>>(out);
}

// round 7
// speedup vs baseline: 2.9710x; 1.0482x over previous
#include <cuda_runtime.h>

#define BB   8
#define CC   64
#define TT   192
#define FFR  128
#define LTm  192               // time view L
#define LFm  128               // freq view L
#define NEL  (BB*CC*TT*FFR)    // 12,582,912
#define HH   4

#define SEGS_T  8
#define SEGS_F  12
#define NBLK_T  (SEGS_T*16)    // 128
#define NBLK_F  (SEGS_F*16)    // 192
#define NT_E    (16*LTm*LTm)
#define NF_E    (16*LFm*LFm)

typedef unsigned short ush;

// ---------------- scratch (device globals; no allocations) ----------------
__device__ ush g_Nh[2][NEL], g_Nl[2][NEL];      // time view, chunked [b][kchunk][t][32]
__device__ ush g_Th[2][NEL], g_Tl[2][NEL];      // freq view, chunked [b][kchunk][f][32]
__device__ float g_GpT[SEGS_T][16][LTm*LTm];
__device__ float g_GpF[SEGS_F][16][LFm*LFm];
__device__ float g_G[2][2][BB*LTm*LTm];
__device__ float g_inv[2][2][BB*LTm];
__device__ float g_mean[2][2][BB*LTm];
__device__ float g_ent[2][BB*LTm];
__device__ float g_qk[2][2][BB*LTm*HH];
__device__ float g_alpha[2][BB*LTm*LTm];
__device__ float g_rowdot[2][BB*LTm];
__device__ float g_part[2][256];

// ---------------- small helpers ----------------
__device__ __forceinline__ float warpSum(float v) {
#pragma unroll
    for (int o = 16; o; o >>= 1) v += __shfl_xor_sync(0xffffffffu, v, o);
    return v;
}
__device__ __forceinline__ float warpMax(float v) {
#pragma unroll
    for (int o = 16; o; o >>= 1) v = fmaxf(v, __shfl_xor_sync(0xffffffffu, v, o));
    return v;
}
__device__ __forceinline__ float blockSum(float v, float* sm) {
    v = warpSum(v);
    int w = threadIdx.x >> 5;
    __syncthreads();
    if ((threadIdx.x & 31) == 0) sm[w] = v;
    __syncthreads();
    float r = 0.f;
    int nw = (blockDim.x + 31) >> 5;
    for (int i = 0; i < nw; i++) r += sm[i];
    return r;
}
__device__ __forceinline__ float blockMax(float v, float* sm) {
    v = warpMax(v);
    int w = threadIdx.x >> 5;
    __syncthreads();
    if ((threadIdx.x & 31) == 0) sm[w] = v;
    __syncthreads();
    float r = -3.402823466e38f;
    int nw = (blockDim.x + 31) >> 5;
    for (int i = 0; i < nw; i++) r = fmaxf(r, sm[i]);
    return r;
}

// ---------------- bf16 / mma helpers ----------------
__device__ __forceinline__ unsigned packbf(float hi, float lo) {   // hi->upper16, lo->lower16
    unsigned r;
    asm("cvt.rn.bf16x2.f32 %0, %1, %2;" : "=r"(r) : "f"(hi), "f"(lo));
    return r;
}
__device__ __forceinline__ void pack8(const float* x, uint4& H, uint4& L) {
    unsigned hw[4], lw[4];
#pragma unroll
    for (int m = 0; m < 4; m++) {
        unsigned h = packbf(x[2 * m + 1], x[2 * m]);
        float a0 = __uint_as_float(h << 16);
        float a1 = __uint_as_float(h & 0xffff0000u);
        hw[m] = h;
        lw[m] = packbf(x[2 * m + 1] - a1, x[2 * m] - a0);
    }
    H = make_uint4(hw[0], hw[1], hw[2], hw[3]);
    L = make_uint4(lw[0], lw[1], lw[2], lw[3]);
}
__device__ __forceinline__ void ldsm4(unsigned* r, unsigned a) {
    asm volatile("ldmatrix.sync.aligned.m8n8.x4.shared.b16 {%0,%1,%2,%3}, [%4];"
                 : "=r"(r[0]), "=r"(r[1]), "=r"(r[2]), "=r"(r[3]) : "r"(a));
}
__device__ __forceinline__ void mma16816(float* d, const unsigned* a, unsigned b0, unsigned b1) {
    asm volatile("mma.sync.aligned.m16n8k16.row.col.f32.bf16.bf16.f32 "
                 "{%0,%1,%2,%3}, {%4,%5,%6,%7}, {%8,%9}, {%0,%1,%2,%3};"
                 : "+f"(d[0]), "+f"(d[1]), "+f"(d[2]), "+f"(d[3])
                 : "r"(a[0]), "r"(a[1]), "r"(a[2]), "r"(a[3]), "r"(b0), "r"(b1));
}
__device__ __forceinline__ unsigned swa(unsigned base, int row, int kbyte) {
    return base + row * 64 + (((((unsigned)kbyte >> 4) ^ (((unsigned)row >> 1) & 3u)) & 3u) << 4);
}
__device__ __forceinline__ void cpa16(unsigned dst, const void* src) {
    asm volatile("cp.async.cg.shared.global [%0], [%1], 16;" :: "r"(dst), "l"(src) : "memory");
}

// ---------------- 1) fused prep: fp32 -> chunked bf16 hi/lo, both views ----------------
// Block = one 32(t) x 32(f) tile of one (which,b,c). Output layouts:
//   time view:  elem index ((bc*4 + f/32)*192 + t)*32 + (f&31)
//   freq view:  elem index ((b*384 + c*6 + t/32)*128 + f)*32 + (t&31)
__global__ void prep_kernel(const float* __restrict__ fs, const float* __restrict__ ft) {
    __shared__ float tile[32][33];
    int z = blockIdx.z;
    int which = z >> 9, bc = z & 511;
    int b = bc >> 6, c = bc & 63;
    const float* src = (which ? ft : fs) + (size_t)bc * TT * FFR;
    int t0 = blockIdx.x * 32, f0 = blockIdx.y * 32;
    int tx = threadIdx.x, ty = threadIdx.y;
#pragma unroll
    for (int i = 0; i < 32; i += 8)
        tile[ty + i][tx] = src[(size_t)(t0 + ty + i) * FFR + f0 + tx];
    __syncthreads();
    int tid = ty * 32 + tx;
    float x[8];
    uint4 Hv, Lv;
    if (tid < 128) {                       // time-view (normal) layout
        int tl = tid >> 2, fg = tid & 3;
#pragma unroll
        for (int j = 0; j < 8; j++) x[j] = tile[tl][fg * 8 + j];
        pack8(x, Hv, Lv);
        size_t o = (((size_t)(bc * 4 + (f0 >> 5)) * 192) + (t0 + tl)) * 32 + fg * 8;
        *(uint4*)(&g_Nh[which][o]) = Hv;
        *(uint4*)(&g_Nl[which][o]) = Lv;
    } else {                               // freq-view (transposed) layout
        int it = tid - 128;
        int tg = it & 3, fl = it >> 2;
#pragma unroll
        for (int j = 0; j < 8; j++) x[j] = tile[tg * 8 + j][fl];
        pack8(x, Hv, Lv);
        size_t o = (((size_t)(b * 384 + c * 6 + (t0 >> 5)) * 128) + (f0 + fl)) * 32 + tg * 8;
        *(uint4*)(&g_Th[which][o]) = Hv;
        *(uint4*)(&g_Tl[which][o]) = Lv;
    }
}

// ---------------- 2) gram: pure cp.async + mma.sync, double-buffered ----------------
template<int TILEB, int TILEE, int NLD>
__device__ __forceinline__ void copy_chunk(unsigned sb, const ush* gh, const ush* gl, int ch, int tid) {
    unsigned dh = sb + (unsigned)(ch & 1) * (2 * TILEB);
    const ush* sh = gh + (size_t)ch * TILEE;
    const ush* sl = gl + (size_t)ch * TILEE;
#pragma unroll
    for (int i = 0; i < NLD; i++) {
        int lin = i * 256 + tid;
        int row = lin >> 2, q = lin & 3;
        unsigned d = (unsigned)(row * 64 + ((q ^ ((row >> 1) & 3)) << 4));
        cpa16(dh + d, sh + lin * 8);
        cpa16(dh + TILEB + d, sl + lin * 8);
    }
    asm volatile("cp.async.commit_group;" ::: "memory");
}

template<int L, int MI, int NP, int NLD>
__device__ __forceinline__ void gram_body(const ush* gh, const ush* gl,
                                          float* __restrict__ Gp, unsigned sb,
                                          int m0w, int j0w)
{
    constexpr int TILEB = L * 64;
    constexpr int TILEE = L * 32;
    int tid = threadIdx.x, lane = tid & 31;
    int t8 = lane >> 3, r8 = lane & 7;
    int aro = r8 + (t8 & 1) * 8, ako = (t8 >> 1) * 16;
    int bro = r8 + (t8 >> 1) * 8, bko = (t8 & 1) * 16;

    float acc[MI][2 * NP][4];
#pragma unroll
    for (int mi = 0; mi < MI; mi++)
#pragma unroll
        for (int n = 0; n < 2 * NP; n++)
#pragma unroll
            for (int u = 0; u < 4; u++) acc[mi][n][u] = 0.f;

    copy_chunk<TILEB, TILEE, NLD>(sb, gh, gl, 0, tid);

    for (int ch = 0; ch < 32; ch++) {
        if (ch < 31) {
            copy_chunk<TILEB, TILEE, NLD>(sb, gh, gl, ch + 1, tid);
            asm volatile("cp.async.wait_group 1;" ::: "memory");
        } else {
            asm volatile("cp.async.wait_group 0;" ::: "memory");
        }
        __syncthreads();
        unsigned hb = sb + (unsigned)(ch & 1) * (2 * TILEB);
        unsigned lb = hb + TILEB;

#pragma unroll
        for (int ks = 0; ks < 2; ks++) {
            int kb = ks * 32;
            unsigned ah[MI][4], bh[NP][4];
#pragma unroll
            for (int mi = 0; mi < MI; mi++) ldsm4(ah[mi], swa(hb, m0w + mi * 16 + aro, kb + ako));
#pragma unroll
            for (int nj = 0; nj < NP; nj++) ldsm4(bh[nj], swa(hb, j0w + nj * 16 + bro, kb + bko));
#pragma unroll
            for (int mi = 0; mi < MI; mi++)
#pragma unroll
                for (int nj = 0; nj < NP; nj++) {
                    mma16816(acc[mi][2 * nj],     ah[mi], bh[nj][0], bh[nj][1]);
                    mma16816(acc[mi][2 * nj + 1], ah[mi], bh[nj][2], bh[nj][3]);
                }
            unsigned bl[NP][4];
#pragma unroll
            for (int nj = 0; nj < NP; nj++) ldsm4(bl[nj], swa(lb, j0w + nj * 16 + bro, kb + bko));
#pragma unroll
            for (int mi = 0; mi < MI; mi++)
#pragma unroll
                for (int nj = 0; nj < NP; nj++) {
                    mma16816(acc[mi][2 * nj],     ah[mi], bl[nj][0], bl[nj][1]);
                    mma16816(acc[mi][2 * nj + 1], ah[mi], bl[nj][2], bl[nj][3]);
                }
            unsigned al[MI][4];
#pragma unroll
            for (int mi = 0; mi < MI; mi++) ldsm4(al[mi], swa(lb, m0w + mi * 16 + aro, kb + ako));
#pragma unroll
            for (int mi = 0; mi < MI; mi++)
#pragma unroll
                for (int nj = 0; nj < NP; nj++) {
                    mma16816(acc[mi][2 * nj],     al[mi], bh[nj][0], bh[nj][1]);
                    mma16816(acc[mi][2 * nj + 1], al[mi], bh[nj][2], bh[nj][3]);
                }
        }
        __syncthreads();
    }

    int rq = lane >> 2, cq = lane & 3;
#pragma unroll
    for (int mi = 0; mi < MI; mi++)
#pragma unroll
        for (int n = 0; n < 2 * NP; n++) {
            int m = m0w + mi * 16 + rq, j = j0w + n * 8 + cq * 2;
            *(float2*)&Gp[(size_t)m * L + j] = make_float2(acc[mi][n][0], acc[mi][n][1]);
            *(float2*)&Gp[(size_t)(m + 8) * L + j] = make_float2(acc[mi][n][2], acc[mi][n][3]);
        }
}

__global__ void __launch_bounds__(256, 1) gram_kernel() {
    extern __shared__ __align__(16) char smraw[];
    unsigned sb = (unsigned)__cvta_generic_to_shared(smraw);
    int wid = threadIdx.x >> 5;
    int bid = blockIdx.x;

    if (bid < NBLK_T) {
        int seg = bid >> 4, bw = bid & 15;
        int which = bw >> 3, b = bw & 7;
        const ush* gh = g_Nh[which] + (size_t)(b * 256 + seg * 32) * (LTm * 32);
        const ush* gl = g_Nl[which] + (size_t)(b * 256 + seg * 32) * (LTm * 32);
        float* Gp = &g_GpT[seg][bw][0];
        int m0w = (wid >> 2) * 96, j0w = (wid & 3) * 48;
        gram_body<LTm, 6, 3, 3>(gh, gl, Gp, sb, m0w, j0w);
    } else {
        int r = bid - NBLK_T;
        int seg = r >> 4, bw = r & 15;
        int which = bw >> 3, b = bw & 7;
        const ush* gh = g_Th[which] + (size_t)(b * 384 + seg * 32) * (LFm * 32);
        const ush* gl = g_Tl[which] + (size_t)(b * 384 + seg * 32) * (LFm * 32);
        float* Gp = &g_GpF[seg][bw][0];
        int m0w = (wid & 3) * 32, j0w = (wid >> 2) * 64;
        gram_body<LFm, 2, 4, 2>(gh, gl, Gp, sb, m0w, j0w);
    }
}

// ---------------- 3) sum partials + fused norms ----------------
__global__ void sumG_kernel() {
    int idx = blockIdx.x * 256 + threadIdx.x;
    if (idx < NT_E) {
        int bw = idx / (LTm * LTm), e = idx % (LTm * LTm);
        int i = e / LTm, j = e % LTm;
        float s = 0.f;
#pragma unroll
        for (int g = 0; g < SEGS_T; g++) s += g_GpT[g][bw][e];
        int which = bw >> 3, b = bw & 7;
        g_G[0][which][(size_t)b * LTm * LTm + e] = s;
        if (i == j) g_inv[0][which][b * LTm + i] = 1.0f / fmaxf(sqrtf(s), 1e-8f);
    } else {
        idx -= NT_E;
        int bw = idx / (LFm * LFm), e = idx % (LFm * LFm);
        int i = e / LFm, j = e % LFm;
        float s = 0.f;
#pragma unroll
        for (int g = 0; g < SEGS_F; g++) s += g_GpF[g][bw][e];
        int which = bw >> 3, b = bw & 7;
        g_G[1][which][(size_t)b * LFm * LFm + e] = s;
        if (i == j) g_inv[1][which][b * LFm + i] = 1.0f / fmaxf(sqrtf(s), 1e-8f);
    }
}

// ---------------- 4) per-row: P, rowmean, softmax(+eps), log / entropy ----------------
__global__ void rowproc_kernel(int view, int L) {
    __shared__ float red[8];
    int l = blockIdx.x, b = blockIdx.y, which = blockIdx.z;
    int m = threadIdx.x;
    float* G = g_G[view][which] + (size_t)b * L * L + (size_t)l * L;
    float invl = g_inv[view][which][b * L + l];
    float invm = g_inv[view][which][b * L + m];
    float pv = 0.5f * (G[m] * invl * invm + 1.0f);

    float s = blockSum(pv, red);
    if (m == 0) g_mean[view][which][b * L + l] = s / (float)L;

    float mx = blockMax(pv, red);
    float e = expf(pv - mx);
    float Z = blockSum(e, red);
    float sp = e / Z + 1e-8f;

    if (which == 0) {
        G[m] = logf(sp + 1e-8f);
    } else {
        G[m] = sp;
        float ent = blockSum(sp * logf(sp + 1e-8f), red);
        if (m == 0) g_ent[view][b * L + l] = ent;
    }
}

// ---------------- 5) tiny MLP ----------------
__global__ void mlp_kernel(int view, int L,
                           const float* __restrict__ Wq, const float* __restrict__ bq,
                           const float* __restrict__ gq, const float* __restrict__ Bq,
                           const float* __restrict__ Wk, const float* __restrict__ bk,
                           const float* __restrict__ gk, const float* __restrict__ Bk) {
    int b = blockIdx.x, sel = blockIdx.y;
    int l = threadIdx.x;
    const float* W  = sel ? Wk : Wq;
    const float* bi = sel ? bk : bq;
    const float* gg = sel ? gk : gq;
    const float* be = sel ? Bk : Bq;
    float x = g_mean[view][sel][b * L + l];
    float h[HH]; float mu = 0.f;
#pragma unroll
    for (int j = 0; j < HH; j++) { h[j] = fmaxf(W[j] * x + bi[j], 0.f); mu += h[j]; }
    mu *= (1.0f / HH);
    float var = 0.f;
#pragma unroll
    for (int j = 0; j < HH; j++) { float d = h[j] - mu; var += d * d; }
    var *= (1.0f / HH);
    float inv = rsqrtf(var + 1e-5f);
#pragma unroll
    for (int j = 0; j < HH; j++)
        g_qk[view][sel][((size_t)b * L + l) * HH + j] = gg[j] * (h[j] - mu) * inv + be[j];
}

// ---------------- 6) alpha + fused ent-dot (replaces colsum) ----------------
__global__ void alpha_kernel(int view, int L) {
    __shared__ float kb[LTm * HH];
    __shared__ float red[8];
    int s = blockIdx.x, b = blockIdx.y;
    int t = threadIdx.x;
    for (int i = t; i < L * HH; i += blockDim.x)
        kb[i] = g_qk[view][1][(size_t)b * L * HH + i];
    float q0 = g_qk[view][0][((size_t)b * L + s) * HH + 0];
    float q1 = g_qk[view][0][((size_t)b * L + s) * HH + 1];
    float q2 = g_qk[view][0][((size_t)b * L + s) * HH + 2];
    float q3 = g_qk[view][0][((size_t)b * L + s) * HH + 3];
    __syncthreads();
    float invScale = rsqrtf(4.0f + 1e-8f);
    float a = (q0 * kb[t * 4 + 0] + q1 * kb[t * 4 + 1] + q2 * kb[t * 4 + 2] + q3 * kb[t * 4 + 3]) * invScale;
    float mx = blockMax(a, red);
    float e = expf(a - mx);
    float Z = blockSum(e, red);
    float al = e / Z;
    g_alpha[view][(size_t)b * L * L + (size_t)s * L + t] = al;
    float rd = blockSum(al * g_ent[view][b * L + t], red);
    if (t == 0) g_rowdot[view][b * L + s] = rd;
}

// ---------------- 7) term2 partials ----------------
__global__ void part_kernel(int view, int L) {
    __shared__ float sal[8][LTm];
    __shared__ float red[8];
    int b = blockIdx.y, s0 = blockIdx.x * 8;
    const float* logPs = g_G[view][0] + (size_t)b * L * L;
    const float* Pt    = g_G[view][1] + (size_t)b * L * L;
    const float* al    = g_alpha[view] + (size_t)b * L * L;
    int k = threadIdx.x;
#pragma unroll
    for (int i = 0; i < 8; i++) sal[i][k] = al[(size_t)(s0 + i) * L + k];
    __syncthreads();
    float m[8];
#pragma unroll
    for (int i = 0; i < 8; i++) m[i] = 0.f;
    for (int t = 0; t < L; t++) {
        float pv = Pt[(size_t)t * L + k];
#pragma unroll
        for (int i = 0; i < 8; i++) m[i] += sal[i][t] * pv;
    }
    float acc = 0.f;
#pragma unroll
    for (int i = 0; i < 8; i++) acc += m[i] * logPs[(size_t)(s0 + i) * L + k];
    float tot = blockSum(acc, red);
    if (k == 0) g_part[view][blockIdx.y * gridDim.x + blockIdx.x] = tot;
}

// ---------------- 8) final deterministic reduction ----------------
__global__ void final_kernel(float* out) {
    __shared__ float red[8];
    int tid = threadIdx.x;
    float t2T = 0.f; for (int i = tid; i < (LTm / 8) * BB; i += 256) t2T += g_part[0][i];
    t2T = blockSum(t2T, red);
    float t2F = 0.f; for (int i = tid; i < (LFm / 8) * BB; i += 256) t2F += g_part[1][i];
    t2F = blockSum(t2F, red);
    float t1T = 0.f; for (int i = tid; i < BB * LTm; i += 256) t1T += g_rowdot[0][i];
    t1T = blockSum(t1T, red);
    float t1F = 0.f; for (int i = tid; i < BB * LFm; i += 256) t1F += g_rowdot[1][i];
    t1F = blockSum(t1F, red);
    if (tid == 0) {
        float lt = (t1T - t2T) / ((float)BB * LTm * LTm + 1e-8f);
        float lf = (t1F - t2F) / ((float)BB * LFm * LFm + 1e-8f);
        out[0] = lt + lf;
    }
}

// ---------------- launch ----------------
extern "C" void kernel_launch(void* const* d_in, const int* in_sizes, int n_in,
                              void* d_out, int out_size) {
    const float* fs  = (const float*)d_in[0];
    const float* ft  = (const float*)d_in[1];
    const float* WqT = (const float*)d_in[2];
    const float* bqT = (const float*)d_in[3];
    const float* gqT = (const float*)d_in[4];
    const float* BqT = (const float*)d_in[5];
    const float* WkT = (const float*)d_in[6];
    const float* bkT = (const float*)d_in[7];
    const float* gkT = (const float*)d_in[8];
    const float* BkT = (const float*)d_in[9];
    const float* WqF = (const float*)d_in[10];
    const float* bqF = (const float*)d_in[11];
    const float* gqF = (const float*)d_in[12];
    const float* BqF = (const float*)d_in[13];
    const float* WkF = (const float*)d_in[14];
    const float* bkF = (const float*)d_in[15];
    const float* gkF = (const float*)d_in[16];
    const float* BkF = (const float*)d_in[17];
    float* out = (float*)d_out;

    prep_kernel<<<dim3(TT / 32, FFR / 32, BB * CC * 2), dim3(32, 8)>>>(fs, ft);

    gram_kernel<<<NBLK_T + NBLK_F, 256, 4 * LTm * 64>>>();

    sumG_kernel<<<(NT_E + NF_E) / 256, 256>>>();

    rowproc_kernel<<<dim3(LTm, BB, 2), LTm>>>(0, LTm);
    rowproc_kernel<<<dim3(LFm, BB, 2), LFm>>>(1, LFm);

    mlp_kernel<<<dim3(BB, 2), LTm>>>(0, LTm, WqT, bqT, gqT, BqT, WkT, bkT, gkT, BkT);
    mlp_kernel<<<dim3(BB, 2), LFm>>>(1, LFm, WqF, bqF, gqF, BqF, WkF, bkF, gkF, BkF);

    alpha_kernel<<<dim3(LTm, BB), LTm>>>(0, LTm);
    alpha_kernel<<<dim3(LFm, BB), LFm>>>(1, LFm);

    part_kernel<<<dim3(LTm / 8, BB), LTm>>>(0, LTm);
    part_kernel<<<dim3(LFm / 8, BB), LFm>>>(1, LFm);

    final_kernel<<<1, 256>>>(out);
}

// round 9
// speedup vs baseline: 4.0289x; 1.3561x over previous
#include <cuda_runtime.h>

#define BB   8
#define CC   64
#define TT   192
#define FFR  128
#define LTm  192
#define LFm  128
#define NEL  (BB*CC*TT*FFR)
#define HH   4

#define SEGS_T  8              // KSEG 1024
#define SEGS_F  6              // KSEG 2048
#define NBLK_T  (SEGS_T*16*3)  // 384
#define NBLK_F  (SEGS_F*16*3)  // 288
#define NT_E    (16*LTm*LTm)
#define NF_E    (16*LFm*LFm)

typedef unsigned short ush;

// ---------------- scratch ----------------
__device__ ush g_Nh[2][NEL], g_Nl[2][NEL];      // time view chunks [b][kchunk][t(192)][32]
__device__ ush g_Th[2][NEL], g_Tl[2][NEL];      // freq view chunks [b][kchunk][f(128)][32]
__device__ float g_GpT[SEGS_T][16][LTm*LTm];
__device__ float g_GpF[SEGS_F][16][LFm*LFm];
__device__ float g_G[2][2][BB*LTm*LTm];
__device__ float g_inv[2][2][BB*LTm];
__device__ float g_mean[2][2][BB*LTm];
__device__ float g_ent[2][BB*LTm];
__device__ float g_qk[2][2][BB*LTm*HH];
__device__ float g_alpha[2][BB*LTm*LTm];
__device__ float g_rowdot[2][BB*LTm];
__device__ float g_part[2][512];

// ---------------- helpers ----------------
__device__ __forceinline__ float warpSum(float v) {
#pragma unroll
    for (int o = 16; o; o >>= 1) v += __shfl_xor_sync(0xffffffffu, v, o);
    return v;
}
__device__ __forceinline__ float warpMax(float v) {
#pragma unroll
    for (int o = 16; o; o >>= 1) v = fmaxf(v, __shfl_xor_sync(0xffffffffu, v, o));
    return v;
}
__device__ __forceinline__ float blockSum(float v, float* sm) {
    v = warpSum(v);
    int w = threadIdx.x >> 5;
    __syncthreads();
    if ((threadIdx.x & 31) == 0) sm[w] = v;
    __syncthreads();
    float r = 0.f;
    int nw = (blockDim.x + 31) >> 5;
    for (int i = 0; i < nw; i++) r += sm[i];
    return r;
}
__device__ __forceinline__ float blockMax(float v, float* sm) {
    v = warpMax(v);
    int w = threadIdx.x >> 5;
    __syncthreads();
    if ((threadIdx.x & 31) == 0) sm[w] = v;
    __syncthreads();
    float r = -3.402823466e38f;
    int nw = (blockDim.x + 31) >> 5;
    for (int i = 0; i < nw; i++) r = fmaxf(r, sm[i]);
    return r;
}
__device__ __forceinline__ unsigned packbf(float hi, float lo) {
    unsigned r;
    asm("cvt.rn.bf16x2.f32 %0, %1, %2;" : "=r"(r) : "f"(hi), "f"(lo));
    return r;
}
__device__ __forceinline__ void pack8(const float* x, uint4& H, uint4& L) {
    unsigned hw[4], lw[4];
#pragma unroll
    for (int m = 0; m < 4; m++) {
        unsigned h = packbf(x[2 * m + 1], x[2 * m]);
        float a0 = __uint_as_float(h << 16);
        float a1 = __uint_as_float(h & 0xffff0000u);
        hw[m] = h;
        lw[m] = packbf(x[2 * m + 1] - a1, x[2 * m] - a0);
    }
    H = make_uint4(hw[0], hw[1], hw[2], hw[3]);
    L = make_uint4(lw[0], lw[1], lw[2], lw[3]);
}
__device__ __forceinline__ void ldsm4(unsigned* r, unsigned a) {
    asm volatile("ldmatrix.sync.aligned.m8n8.x4.shared.b16 {%0,%1,%2,%3}, [%4];"
                 : "=r"(r[0]), "=r"(r[1]), "=r"(r[2]), "=r"(r[3]) : "r"(a));
}
__device__ __forceinline__ void mma16816(float* d, const unsigned* a, unsigned b0, unsigned b1) {
    asm volatile("mma.sync.aligned.m16n8k16.row.col.f32.bf16.bf16.f32 "
                 "{%0,%1,%2,%3}, {%4,%5,%6,%7}, {%8,%9}, {%0,%1,%2,%3};"
                 : "+f"(d[0]), "+f"(d[1]), "+f"(d[2]), "+f"(d[3])
                 : "r"(a[0]), "r"(a[1]), "r"(a[2]), "r"(a[3]), "r"(b0), "r"(b1));
}
__device__ __forceinline__ unsigned swa(unsigned base, int row, int kbyte) {
    return base + row * 64 + (((((unsigned)kbyte >> 4) ^ (((unsigned)row >> 1) & 3u)) & 3u) << 4);
}
__device__ __forceinline__ void cpa16(unsigned dst, const void* src) {
    asm volatile("cp.async.cg.shared.global [%0], [%1], 16;" :: "r"(dst), "l"(src) : "memory");
}

// ---------------- 1) prep: fp32 -> chunked bf16 hi/lo, both views ----------------
__global__ void prep_kernel(const float* __restrict__ fs, const float* __restrict__ ft) {
    __shared__ float tile[32][33];
    int z = blockIdx.z;
    int which = z >> 9, bc = z & 511;
    int b = bc >> 6, c = bc & 63;
    const float* src = (which ? ft : fs) + (size_t)bc * TT * FFR;
    int t0 = blockIdx.x * 32, f0 = blockIdx.y * 32;
    int tx = threadIdx.x, ty = threadIdx.y;
#pragma unroll
    for (int i = 0; i < 32; i += 8)
        tile[ty + i][tx] = src[(size_t)(t0 + ty + i) * FFR + f0 + tx];
    __syncthreads();
    int tid = ty * 32 + tx;
    float x[8];
    uint4 Hv, Lv;
    if (tid < 128) {
        int tl = tid >> 2, fg = tid & 3;
#pragma unroll
        for (int j = 0; j < 8; j++) x[j] = tile[tl][fg * 8 + j];
        pack8(x, Hv, Lv);
        size_t o = (((size_t)(bc * 4 + (f0 >> 5)) * 192) + (t0 + tl)) * 32 + fg * 8;
        *(uint4*)(&g_Nh[which][o]) = Hv;
        *(uint4*)(&g_Nl[which][o]) = Lv;
    } else {
        int it = tid - 128;
        int tg = it & 3, fl = it >> 2;
#pragma unroll
        for (int j = 0; j < 8; j++) x[j] = tile[tg * 8 + j][fl];
        pack8(x, Hv, Lv);
        size_t o = (((size_t)(b * 384 + c * 6 + (t0 >> 5)) * 128) + (f0 + fl)) * 32 + tg * 8;
        *(uint4*)(&g_Th[which][o]) = Hv;
        *(uint4*)(&g_Tl[which][o]) = Lv;
    }
}

// ---------------- 2) triangular-pair gram: cp.async + mma.sync ----------------
// CTA = one tile pair (TM x TM) x one K segment. 4 warps (2x2). Diagonal pairs
// share one smem tile for A and B.
template<int L, int TM, int MI, int NP, int NCH, int PLD>
__device__ __forceinline__ void gram_body(const ush* gh, const ush* gl,
                                          int rows0, int rows1, bool diag,
                                          float* __restrict__ Gp, unsigned sb)
{
    constexpr int TMB = TM * 64;
    constexpr int BUFB = 4 * TMB;
    int tid = threadIdx.x, wid = tid >> 5, lane = tid & 31;
    int t8 = lane >> 3, r8 = lane & 7;
    int aro = r8 + (t8 & 1) * 8, ako = (t8 >> 1) * 16;
    int bro = r8 + (t8 >> 1) * 8, bko = (t8 & 1) * 16;
    int m0w = (wid >> 1) * (TM / 2), j0w = (wid & 1) * (TM / 2);

    float acc[MI][2 * NP][4];
#pragma unroll
    for (int mi = 0; mi < MI; mi++)
#pragma unroll
        for (int n = 0; n < 2 * NP; n++)
#pragma unroll
            for (int u = 0; u < 4; u++) acc[mi][n][u] = 0.f;

    auto copy_chunk = [&](int ch) {
        unsigned dst = sb + (unsigned)(ch & 1) * BUFB;
        const ush* sh = gh + ((size_t)ch * L + rows0) * 32;
        const ush* sl = gl + ((size_t)ch * L + rows0) * 32;
#pragma unroll
        for (int i = 0; i < PLD; i++) {
            int lin = i * 128 + tid;
            int row = lin >> 2, q = lin & 3;
            unsigned d = dst + (unsigned)(row * 64 + ((q ^ ((row >> 1) & 3)) << 4));
            cpa16(d, sh + row * 32 + q * 8);
            cpa16(d + TMB, sl + row * 32 + q * 8);
        }
        if (!diag) {
            const ush* sh2 = gh + ((size_t)ch * L + rows1) * 32;
            const ush* sl2 = gl + ((size_t)ch * L + rows1) * 32;
#pragma unroll
            for (int i = 0; i < PLD; i++) {
                int lin = i * 128 + tid;
                int row = lin >> 2, q = lin & 3;
                unsigned d = dst + 2 * TMB + (unsigned)(row * 64 + ((q ^ ((row >> 1) & 3)) << 4));
                cpa16(d, sh2 + row * 32 + q * 8);
                cpa16(d + TMB, sl2 + row * 32 + q * 8);
            }
        }
        asm volatile("cp.async.commit_group;" ::: "memory");
    };

    copy_chunk(0);
    for (int ch = 0; ch < NCH; ch++) {
        if (ch < NCH - 1) {
            copy_chunk(ch + 1);
            asm volatile("cp.async.wait_group 1;" ::: "memory");
        } else {
            asm volatile("cp.async.wait_group 0;" ::: "memory");
        }
        __syncthreads();
        unsigned abase = sb + (unsigned)(ch & 1) * BUFB;
        unsigned bbase = diag ? abase : abase + 2 * TMB;

#pragma unroll
        for (int ks = 0; ks < 2; ks++) {
            int kb = ks * 32;
            unsigned ah[MI][4], bh[NP][4];
#pragma unroll
            for (int mi = 0; mi < MI; mi++) ldsm4(ah[mi], swa(abase, m0w + mi * 16 + aro, kb + ako));
#pragma unroll
            for (int nj = 0; nj < NP; nj++) ldsm4(bh[nj], swa(bbase, j0w + nj * 16 + bro, kb + bko));
#pragma unroll
            for (int mi = 0; mi < MI; mi++)
#pragma unroll
                for (int nj = 0; nj < NP; nj++) {
                    mma16816(acc[mi][2 * nj],     ah[mi], bh[nj][0], bh[nj][1]);
                    mma16816(acc[mi][2 * nj + 1], ah[mi], bh[nj][2], bh[nj][3]);
                }
            unsigned bl[NP][4];
#pragma unroll
            for (int nj = 0; nj < NP; nj++) ldsm4(bl[nj], swa(bbase + TMB, j0w + nj * 16 + bro, kb + bko));
#pragma unroll
            for (int mi = 0; mi < MI; mi++)
#pragma unroll
                for (int nj = 0; nj < NP; nj++) {
                    mma16816(acc[mi][2 * nj],     ah[mi], bl[nj][0], bl[nj][1]);
                    mma16816(acc[mi][2 * nj + 1], ah[mi], bl[nj][2], bl[nj][3]);
                }
            unsigned al[MI][4];
#pragma unroll
            for (int mi = 0; mi < MI; mi++) ldsm4(al[mi], swa(abase + TMB, m0w + mi * 16 + aro, kb + ako));
#pragma unroll
            for (int mi = 0; mi < MI; mi++)
#pragma unroll
                for (int nj = 0; nj < NP; nj++) {
                    mma16816(acc[mi][2 * nj],     al[mi], bh[nj][0], bh[nj][1]);
                    mma16816(acc[mi][2 * nj + 1], al[mi], bh[nj][2], bh[nj][3]);
                }
        }
        __syncthreads();
    }

    int rq = lane >> 2, cq = lane & 3;
#pragma unroll
    for (int mi = 0; mi < MI; mi++)
#pragma unroll
        for (int n = 0; n < 2 * NP; n++) {
            int m = rows0 + m0w + mi * 16 + rq, j = rows1 + j0w + n * 8 + cq * 2;
            *(float2*)&Gp[(size_t)m * L + j] = make_float2(acc[mi][n][0], acc[mi][n][1]);
            *(float2*)&Gp[(size_t)(m + 8) * L + j] = make_float2(acc[mi][n][2], acc[mi][n][3]);
        }
}

__global__ void __launch_bounds__(128) gram_kernel() {
    extern __shared__ __align__(16) char smraw[];
    unsigned sb = (unsigned)__cvta_generic_to_shared(smraw);
    int bid = blockIdx.x;
    if (bid < NBLK_T) {
        int seg = bid / 48, r = bid % 48, bw = r / 3, pair = r % 3;
        int which = bw >> 3, b = bw & 7;
        int pi = (pair == 2) ? 1 : 0, pj = (pair == 0) ? 0 : 1;
        const ush* gh = g_Nh[which] + (size_t)(b * 256 + seg * 32) * (LTm * 32);
        const ush* gl = g_Nl[which] + (size_t)(b * 256 + seg * 32) * (LTm * 32);
        gram_body<LTm, 96, 3, 3, 32, 3>(gh, gl, pi * 96, pj * 96, pair != 1,
                                        &g_GpT[seg][bw][0], sb);
    } else {
        int r0 = bid - NBLK_T;
        int seg = r0 / 48, r = r0 % 48, bw = r / 3, pair = r % 3;
        int which = bw >> 3, b = bw & 7;
        int pi = (pair == 2) ? 1 : 0, pj = (pair == 0) ? 0 : 1;
        const ush* gh = g_Th[which] + (size_t)(b * 384 + seg * 64) * (LFm * 32);
        const ush* gl = g_Tl[which] + (size_t)(b * 384 + seg * 64) * (LFm * 32);
        gram_body<LFm, 64, 2, 2, 64, 2>(gh, gl, pi * 64, pj * 64, pair != 1,
                                        &g_GpF[seg][bw][0], sb);
    }
}

// ---------------- 3) sum partials + mirror + fused norms ----------------
__global__ void sumG_kernel() {
    int idx = blockIdx.x * 256 + threadIdx.x;
    if (idx < NT_E) {
        int bw = idx / (LTm * LTm), e = idx % (LTm * LTm);
        int i = e / LTm, j = e % LTm;
        int es = (i >= 96 && j < 96) ? (j * LTm + i) : e;
        float s = 0.f;
#pragma unroll
        for (int g = 0; g < SEGS_T; g++) s += g_GpT[g][bw][es];
        int which = bw >> 3, b = bw & 7;
        g_G[0][which][(size_t)b * LTm * LTm + e] = s;
        if (i == j) g_inv[0][which][b * LTm + i] = 1.0f / fmaxf(sqrtf(s), 1e-8f);
    } else {
        idx -= NT_E;
        int bw = idx / (LFm * LFm), e = idx % (LFm * LFm);
        int i = e / LFm, j = e % LFm;
        int es = (i >= 64 && j < 64) ? (j * LFm + i) : e;
        float s = 0.f;
#pragma unroll
        for (int g = 0; g < SEGS_F; g++) s += g_GpF[g][bw][es];
        int which = bw >> 3, b = bw & 7;
        g_G[1][which][(size_t)b * LFm * LFm + e] = s;
        if (i == j) g_inv[1][which][b * LFm + i] = 1.0f / fmaxf(sqrtf(s), 1e-8f);
    }
}

// ---------------- 4) rowproc: warp-per-row, both views, no barriers ----------------
__global__ void rowproc2_kernel() {
    int w = blockIdx.x * 8 + (threadIdx.x >> 5);
    int lane = threadIdx.x & 31;
    int view, which, b, l, L;
    if (w < 3072) { view = 0; L = 192; which = w / 1536; int r = w % 1536; b = r / 192; l = r % 192; }
    else { int w2 = w - 3072; view = 1; L = 128; which = w2 / 1024; int r = w2 % 1024; b = r / 128; l = r % 128; }
    float* G = g_G[view][which] + ((size_t)b * L + l) * L;
    const float* inv = g_inv[view][which] + b * L;
    float invl = inv[l];
    int ne = L >> 5;
    float pv[6];
    float s = 0.f, mx = -3.402823466e38f;
    for (int e = 0; e < ne; e++) {
        int m = lane + e * 32;
        pv[e] = 0.5f * (G[m] * invl * inv[m] + 1.0f);
        s += pv[e];
        mx = fmaxf(mx, pv[e]);
    }
    s = warpSum(s);
    mx = warpMax(mx);
    if (lane == 0) g_mean[view][which][b * L + l] = s / (float)L;
    float ex[6], Z = 0.f;
    for (int e = 0; e < ne; e++) { ex[e] = expf(pv[e] - mx); Z += ex[e]; }
    Z = warpSum(Z);
    float ent = 0.f;
    for (int e = 0; e < ne; e++) {
        int m = lane + e * 32;
        float sp = ex[e] / Z + 1e-8f;
        if (which == 0) G[m] = logf(sp + 1e-8f);
        else { G[m] = sp; ent += sp * logf(sp + 1e-8f); }
    }
    if (which == 1) {
        ent = warpSum(ent);
        if (lane == 0) g_ent[view][b * L + l] = ent;
    }
}

// ---------------- 5) MLP (both views) ----------------
__global__ void mlp_kernel(const float* __restrict__ WqT, const float* __restrict__ bqT,
                           const float* __restrict__ gqT, const float* __restrict__ BqT,
                           const float* __restrict__ WkT, const float* __restrict__ bkT,
                           const float* __restrict__ gkT, const float* __restrict__ BkT,
                           const float* __restrict__ WqF, const float* __restrict__ bqF,
                           const float* __restrict__ gqF, const float* __restrict__ BqF,
                           const float* __restrict__ WkF, const float* __restrict__ bkF,
                           const float* __restrict__ gkF, const float* __restrict__ BkF) {
    int b = blockIdx.x, sel = blockIdx.y, view = blockIdx.z;
    int L = view ? LFm : LTm;
    int l = threadIdx.x;
    if (l >= L) return;
    const float* W  = view ? (sel ? WkF : WqF) : (sel ? WkT : WqT);
    const float* bi = view ? (sel ? bkF : bqF) : (sel ? bkT : bqT);
    const float* gg = view ? (sel ? gkF : gqF) : (sel ? gkT : gqT);
    const float* be = view ? (sel ? BkF : BqF) : (sel ? BkT : BqT);
    float x = g_mean[view][sel][b * L + l];
    float h[HH]; float mu = 0.f;
#pragma unroll
    for (int j = 0; j < HH; j++) { h[j] = fmaxf(W[j] * x + bi[j], 0.f); mu += h[j]; }
    mu *= (1.0f / HH);
    float var = 0.f;
#pragma unroll
    for (int j = 0; j < HH; j++) { float d = h[j] - mu; var += d * d; }
    var *= (1.0f / HH);
    float inv = rsqrtf(var + 1e-5f);
#pragma unroll
    for (int j = 0; j < HH; j++)
        g_qk[view][sel][((size_t)b * L + l) * HH + j] = gg[j] * (h[j] - mu) * inv + be[j];
}

// ---------------- 6) alpha + fused ent-dot (both views) ----------------
__global__ void alpha_kernel() {
    __shared__ float kb[LTm * HH];
    __shared__ float red[8];
    int s = blockIdx.x, b = blockIdx.y, view = blockIdx.z;
    int L = view ? LFm : LTm;
    if (s >= L) return;
    int t = threadIdx.x;
    for (int i = t; i < L * HH; i += blockDim.x)
        kb[i] = g_qk[view][1][(size_t)b * L * HH + i];
    float q0 = g_qk[view][0][((size_t)b * L + s) * HH + 0];
    float q1 = g_qk[view][0][((size_t)b * L + s) * HH + 1];
    float q2 = g_qk[view][0][((size_t)b * L + s) * HH + 2];
    float q3 = g_qk[view][0][((size_t)b * L + s) * HH + 3];
    __syncthreads();
    float a = -3.402823466e38f;
    if (t < L) {
        float invScale = rsqrtf(4.0f + 1e-8f);
        a = (q0 * kb[t * 4 + 0] + q1 * kb[t * 4 + 1] + q2 * kb[t * 4 + 2] + q3 * kb[t * 4 + 3]) * invScale;
    }
    float mx = blockMax(a, red);
    float e = (t < L) ? expf(a - mx) : 0.f;
    float Z = blockSum(e, red);
    float al = e / Z;
    if (t < L) g_alpha[view][(size_t)b * L * L + (size_t)s * L + t] = al;
    float rd = blockSum((t < L) ? al * g_ent[view][b * L + t] : 0.f, red);
    if (t == 0) g_rowdot[view][b * L + s] = rd;
}

// ---------------- 7) term2 partials (both views) ----------------
__global__ void part_kernel() {
    __shared__ float salT[LTm][8];
    __shared__ float red[8];
    int view = blockIdx.z, b = blockIdx.y;
    int L = view ? LFm : LTm;
    if (blockIdx.x * 8 >= L) {
        if (threadIdx.x == 0) g_part[view][b * 24 + blockIdx.x] = 0.f;
        return;
    }
    int s0 = blockIdx.x * 8;
    const float* logPs = g_G[view][0] + (size_t)b * L * L;
    const float* Pt    = g_G[view][1] + (size_t)b * L * L;
    const float* al    = g_alpha[view] + (size_t)b * L * L;
    int k = threadIdx.x;
    if (k < L) {
#pragma unroll
        for (int i = 0; i < 8; i++) salT[k][i] = al[(size_t)(s0 + i) * L + k];
    }
    __syncthreads();
    float m[8];
#pragma unroll
    for (int i = 0; i < 8; i++) m[i] = 0.f;
    int kc = (k < L) ? k : 0;
#pragma unroll 2
    for (int t = 0; t < L; t++) {
        float4 a0 = *(const float4*)&salT[t][0];
        float4 a1 = *(const float4*)&salT[t][4];
        float pv = Pt[(size_t)t * L + kc];
        m[0] += a0.x * pv; m[1] += a0.y * pv; m[2] += a0.z * pv; m[3] += a0.w * pv;
        m[4] += a1.x * pv; m[5] += a1.y * pv; m[6] += a1.z * pv; m[7] += a1.w * pv;
    }
    float acc = 0.f;
    if (k < L) {
#pragma unroll
        for (int i = 0; i < 8; i++) acc += m[i] * logPs[(size_t)(s0 + i) * L + k];
    }
    float tot = blockSum(acc, red);
    if (k == 0) g_part[view][b * 24 + blockIdx.x] = tot;
}

// ---------------- 8) final reduction ----------------
__global__ void final_kernel(float* out) {
    __shared__ float red[8];
    int tid = threadIdx.x;
    float t2T = 0.f; for (int i = tid; i < 24 * BB; i += 256) t2T += g_part[0][i];
    t2T = blockSum(t2T, red);
    float t2F = 0.f; for (int i = tid; i < 24 * BB; i += 256) t2F += g_part[1][i];
    t2F = blockSum(t2F, red);
    float t1T = 0.f; for (int i = tid; i < BB * LTm; i += 256) t1T += g_rowdot[0][i];
    t1T = blockSum(t1T, red);
    float t1F = 0.f; for (int i = tid; i < BB * LFm; i += 256) t1F += g_rowdot[1][i];
    t1F = blockSum(t1F, red);
    if (tid == 0) {
        float lt = (t1T - t2T) / ((float)BB * LTm * LTm + 1e-8f);
        float lf = (t1F - t2F) / ((float)BB * LFm * LFm + 1e-8f);
        out[0] = lt + lf;
    }
}

// ---------------- launch ----------------
extern "C" void kernel_launch(void* const* d_in, const int* in_sizes, int n_in,
                              void* d_out, int out_size) {
    const float* fs  = (const float*)d_in[0];
    const float* ft  = (const float*)d_in[1];
    float* out = (float*)d_out;

    prep_kernel<<<dim3(TT / 32, FFR / 32, BB * CC * 2), dim3(32, 8)>>>(fs, ft);

    gram_kernel<<<NBLK_T + NBLK_F, 128, 49152>>>();

    sumG_kernel<<<(NT_E + NF_E) / 256, 256>>>();

    rowproc2_kernel<<<640, 256>>>();

    mlp_kernel<<<dim3(BB, 2, 2), 192>>>(
        (const float*)d_in[2], (const float*)d_in[3], (const float*)d_in[4], (const float*)d_in[5],
        (const float*)d_in[6], (const float*)d_in[7], (const float*)d_in[8], (const float*)d_in[9],
        (const float*)d_in[10], (const float*)d_in[11], (const float*)d_in[12], (const float*)d_in[13],
        (const float*)d_in[14], (const float*)d_in[15], (const float*)d_in[16], (const float*)d_in[17]);

    alpha_kernel<<<dim3(LTm, BB, 2), 192>>>();

    part_kernel<<<dim3(24, BB, 2), 192>>>();

    final_kernel<<<1, 256>>>(out);
}

// round 10
// speedup vs baseline: 4.0320x; 1.0008x over previous
#include <cuda_runtime.h>

#define BB   8
#define CC   64
#define TT   192
#define FFR  128
#define LTm  192
#define LFm  128
#define NEL  (BB*CC*TT*FFR)
#define HH   4

#define SEGS_T  8              // KSEG 1024
#define SEGS_F  6              // KSEG 2048
#define NBLK_T  (SEGS_T*16*3)  // 384
#define NBLK_F  (SEGS_F*16*3)  // 288
#define NT_E    (16*LTm*LTm)
#define NF_E    (16*LFm*LFm)

typedef unsigned short ush;

// ---------------- scratch ----------------
__device__ ush g_Nh[2][NEL], g_Nl[2][NEL];      // time view chunks [b][kchunk][t(192)][32]
__device__ ush g_Th[2][NEL], g_Tl[2][NEL];      // freq view chunks [b][kchunk][f(128)][32]
__device__ float g_GpT[SEGS_T][16][LTm*LTm];
__device__ float g_GpF[SEGS_F][16][LFm*LFm];
__device__ float g_G[2][2][BB*LTm*LTm];
__device__ float g_inv[2][2][BB*LTm];
__device__ float g_mean[2][2][BB*LTm];
__device__ float g_ent[2][BB*LTm];
__device__ float g_qk[2][2][BB*LTm*HH];
__device__ float g_alpha[2][BB*LTm*LTm];
__device__ float g_rowdot[2][BB*LTm];
__device__ float g_part[2][512];

// ---------------- helpers ----------------
__device__ __forceinline__ float warpSum(float v) {
#pragma unroll
    for (int o = 16; o; o >>= 1) v += __shfl_xor_sync(0xffffffffu, v, o);
    return v;
}
__device__ __forceinline__ float warpMax(float v) {
#pragma unroll
    for (int o = 16; o; o >>= 1) v = fmaxf(v, __shfl_xor_sync(0xffffffffu, v, o));
    return v;
}
__device__ __forceinline__ float blockSum(float v, float* sm) {
    v = warpSum(v);
    int w = threadIdx.x >> 5;
    __syncthreads();
    if ((threadIdx.x & 31) == 0) sm[w] = v;
    __syncthreads();
    float r = 0.f;
    int nw = (blockDim.x + 31) >> 5;
    for (int i = 0; i < nw; i++) r += sm[i];
    return r;
}
__device__ __forceinline__ float blockMax(float v, float* sm) {
    v = warpMax(v);
    int w = threadIdx.x >> 5;
    __syncthreads();
    if ((threadIdx.x & 31) == 0) sm[w] = v;
    __syncthreads();
    float r = -3.402823466e38f;
    int nw = (blockDim.x + 31) >> 5;
    for (int i = 0; i < nw; i++) r = fmaxf(r, sm[i]);
    return r;
}
__device__ __forceinline__ unsigned packbf(float hi, float lo) {
    unsigned r;
    asm("cvt.rn.bf16x2.f32 %0, %1, %2;" : "=r"(r) : "f"(hi), "f"(lo));
    return r;
}
__device__ __forceinline__ void pack8(const float* x, uint4& H, uint4& L) {
    unsigned hw[4], lw[4];
#pragma unroll
    for (int m = 0; m < 4; m++) {
        unsigned h = packbf(x[2 * m + 1], x[2 * m]);
        float a0 = __uint_as_float(h << 16);
        float a1 = __uint_as_float(h & 0xffff0000u);
        hw[m] = h;
        lw[m] = packbf(x[2 * m + 1] - a1, x[2 * m] - a0);
    }
    H = make_uint4(hw[0], hw[1], hw[2], hw[3]);
    L = make_uint4(lw[0], lw[1], lw[2], lw[3]);
}
__device__ __forceinline__ void ldsm4(unsigned* r, unsigned a) {
    asm volatile("ldmatrix.sync.aligned.m8n8.x4.shared.b16 {%0,%1,%2,%3}, [%4];"
                 : "=r"(r[0]), "=r"(r[1]), "=r"(r[2]), "=r"(r[3]) : "r"(a));
}
__device__ __forceinline__ void mma16816(float* d, const unsigned* a, unsigned b0, unsigned b1) {
    asm volatile("mma.sync.aligned.m16n8k16.row.col.f32.bf16.bf16.f32 "
                 "{%0,%1,%2,%3}, {%4,%5,%6,%7}, {%8,%9}, {%0,%1,%2,%3};"
                 : "+f"(d[0]), "+f"(d[1]), "+f"(d[2]), "+f"(d[3])
                 : "r"(a[0]), "r"(a[1]), "r"(a[2]), "r"(a[3]), "r"(b0), "r"(b1));
}
__device__ __forceinline__ unsigned swa(unsigned base, int row, int kbyte) {
    return base + row * 64 + (((((unsigned)kbyte >> 4) ^ (((unsigned)row >> 1) & 3u)) & 3u) << 4);
}
__device__ __forceinline__ void cpa16(unsigned dst, const void* src) {
    asm volatile("cp.async.cg.shared.global [%0], [%1], 16;" :: "r"(dst), "l"(src) : "memory");
}

// ---------------- 1) prep: fp32 -> chunked bf16 hi/lo, both views ----------------
__global__ void prep_kernel(const float* __restrict__ fs, const float* __restrict__ ft) {
    __shared__ float tile[32][33];
    int z = blockIdx.z;
    int which = z >> 9, bc = z & 511;
    int b = bc >> 6, c = bc & 63;
    const float* src = (which ? ft : fs) + (size_t)bc * TT * FFR;
    int t0 = blockIdx.x * 32, f0 = blockIdx.y * 32;
    int tx = threadIdx.x, ty = threadIdx.y;
#pragma unroll
    for (int i = 0; i < 32; i += 8)
        tile[ty + i][tx] = src[(size_t)(t0 + ty + i) * FFR + f0 + tx];
    __syncthreads();
    int tid = ty * 32 + tx;
    float x[8];
    uint4 Hv, Lv;
    if (tid < 128) {
        int tl = tid >> 2, fg = tid & 3;
#pragma unroll
        for (int j = 0; j < 8; j++) x[j] = tile[tl][fg * 8 + j];
        pack8(x, Hv, Lv);
        size_t o = (((size_t)(bc * 4 + (f0 >> 5)) * 192) + (t0 + tl)) * 32 + fg * 8;
        *(uint4*)(&g_Nh[which][o]) = Hv;
        *(uint4*)(&g_Nl[which][o]) = Lv;
    } else {
        int it = tid - 128;
        int tg = it & 3, fl = it >> 2;
#pragma unroll
        for (int j = 0; j < 8; j++) x[j] = tile[tg * 8 + j][fl];
        pack8(x, Hv, Lv);
        size_t o = (((size_t)(b * 384 + c * 6 + (t0 >> 5)) * 128) + (f0 + fl)) * 32 + tg * 8;
        *(uint4*)(&g_Th[which][o]) = Hv;
        *(uint4*)(&g_Tl[which][o]) = Lv;
    }
}

// ---------------- 2) triangular-pair gram: chunk-PAIR pipelined cp.async + mma ----------------
// CTA = one tile pair (TM x TM) x one K segment. Stage holds TWO 32-K
// subchunks (K=64 per barrier); 2 stages double-buffered.
template<int L, int TM, int MI, int NP, int NCH2, int PLD>
__device__ __forceinline__ void gram_body(const ush* gh, const ush* gl,
                                          int rows0, int rows1, bool diag,
                                          float* __restrict__ Gp, unsigned sb)
{
    constexpr int TMB = TM * 64;        // bytes of one 32-k tile
    constexpr int STG = 8 * TMB;        // 2 subchunks x 4 tiles
    int tid = threadIdx.x, wid = tid >> 5, lane = tid & 31;
    int t8 = lane >> 3, r8 = lane & 7;
    int aro = r8 + (t8 & 1) * 8, ako = (t8 >> 1) * 16;
    int bro = r8 + (t8 >> 1) * 8, bko = (t8 & 1) * 16;
    int m0w = (wid >> 1) * (TM / 2), j0w = (wid & 1) * (TM / 2);

    float acc[MI][2 * NP][4];
#pragma unroll
    for (int mi = 0; mi < MI; mi++)
#pragma unroll
        for (int n = 0; n < 2 * NP; n++)
#pragma unroll
            for (int u = 0; u < 4; u++) acc[mi][n][u] = 0.f;

    auto copy_pair = [&](int cc) {
        unsigned dst0 = sb + (unsigned)(cc & 1) * STG;
#pragma unroll
        for (int s = 0; s < 2; s++) {
            int ch = 2 * cc + s;
            unsigned dst = dst0 + (unsigned)s * (4 * TMB);
            const ush* sh = gh + ((size_t)ch * L + rows0) * 32;
            const ush* sl = gl + ((size_t)ch * L + rows0) * 32;
#pragma unroll
            for (int i = 0; i < PLD; i++) {
                int lin = i * 128 + tid;
                int row = lin >> 2, q = lin & 3;
                unsigned d = dst + (unsigned)(row * 64 + ((q ^ ((row >> 1) & 3)) << 4));
                cpa16(d, sh + row * 32 + q * 8);
                cpa16(d + TMB, sl + row * 32 + q * 8);
            }
            if (!diag) {
                const ush* sh2 = gh + ((size_t)ch * L + rows1) * 32;
                const ush* sl2 = gl + ((size_t)ch * L + rows1) * 32;
#pragma unroll
                for (int i = 0; i < PLD; i++) {
                    int lin = i * 128 + tid;
                    int row = lin >> 2, q = lin & 3;
                    unsigned d = dst + 2 * TMB + (unsigned)(row * 64 + ((q ^ ((row >> 1) & 3)) << 4));
                    cpa16(d, sh2 + row * 32 + q * 8);
                    cpa16(d + TMB, sl2 + row * 32 + q * 8);
                }
            }
        }
        asm volatile("cp.async.commit_group;" ::: "memory");
    };

    copy_pair(0);
    for (int cc = 0; cc < NCH2; cc++) {
        if (cc + 1 < NCH2) {
            copy_pair(cc + 1);
            asm volatile("cp.async.wait_group 1;" ::: "memory");
        } else {
            asm volatile("cp.async.wait_group 0;" ::: "memory");
        }
        __syncthreads();
        unsigned stg = sb + (unsigned)(cc & 1) * STG;

#pragma unroll
        for (int sub = 0; sub < 2; sub++) {
            unsigned abase = stg + (unsigned)sub * (4 * TMB);
            unsigned bbase = diag ? abase : abase + 2 * TMB;
#pragma unroll
            for (int ks = 0; ks < 2; ks++) {
                int kb = ks * 32;
                unsigned ah[MI][4], bh[NP][4];
#pragma unroll
                for (int mi = 0; mi < MI; mi++) ldsm4(ah[mi], swa(abase, m0w + mi * 16 + aro, kb + ako));
#pragma unroll
                for (int nj = 0; nj < NP; nj++) ldsm4(bh[nj], swa(bbase, j0w + nj * 16 + bro, kb + bko));
#pragma unroll
                for (int mi = 0; mi < MI; mi++)
#pragma unroll
                    for (int nj = 0; nj < NP; nj++) {
                        mma16816(acc[mi][2 * nj],     ah[mi], bh[nj][0], bh[nj][1]);
                        mma16816(acc[mi][2 * nj + 1], ah[mi], bh[nj][2], bh[nj][3]);
                    }
                unsigned bl[NP][4];
#pragma unroll
                for (int nj = 0; nj < NP; nj++) ldsm4(bl[nj], swa(bbase + TMB, j0w + nj * 16 + bro, kb + bko));
#pragma unroll
                for (int mi = 0; mi < MI; mi++)
#pragma unroll
                    for (int nj = 0; nj < NP; nj++) {
                        mma16816(acc[mi][2 * nj],     ah[mi], bl[nj][0], bl[nj][1]);
                        mma16816(acc[mi][2 * nj + 1], ah[mi], bl[nj][2], bl[nj][3]);
                    }
                unsigned al[MI][4];
#pragma unroll
                for (int mi = 0; mi < MI; mi++) ldsm4(al[mi], swa(abase + TMB, m0w + mi * 16 + aro, kb + ako));
#pragma unroll
                for (int mi = 0; mi < MI; mi++)
#pragma unroll
                    for (int nj = 0; nj < NP; nj++) {
                        mma16816(acc[mi][2 * nj],     al[mi], bh[nj][0], bh[nj][1]);
                        mma16816(acc[mi][2 * nj + 1], al[mi], bh[nj][2], bh[nj][3]);
                    }
            }
        }
        __syncthreads();
    }

    int rq = lane >> 2, cq = lane & 3;
#pragma unroll
    for (int mi = 0; mi < MI; mi++)
#pragma unroll
        for (int n = 0; n < 2 * NP; n++) {
            int m = rows0 + m0w + mi * 16 + rq, j = rows1 + j0w + n * 8 + cq * 2;
            *(float2*)&Gp[(size_t)m * L + j] = make_float2(acc[mi][n][0], acc[mi][n][1]);
            *(float2*)&Gp[(size_t)(m + 8) * L + j] = make_float2(acc[mi][n][2], acc[mi][n][3]);
        }
}

__global__ void __launch_bounds__(128) gram_kernel() {
    extern __shared__ __align__(16) char smraw[];
    unsigned sb = (unsigned)__cvta_generic_to_shared(smraw);
    int bid = blockIdx.x;
    if (bid < NBLK_T) {
        int seg = bid / 48, r = bid % 48, bw = r / 3, pair = r % 3;
        int which = bw >> 3, b = bw & 7;
        int pi = (pair == 2) ? 1 : 0, pj = (pair == 0) ? 0 : 1;
        const ush* gh = g_Nh[which] + (size_t)(b * 256 + seg * 32) * (LTm * 32);
        const ush* gl = g_Nl[which] + (size_t)(b * 256 + seg * 32) * (LTm * 32);
        gram_body<LTm, 96, 3, 3, 16, 3>(gh, gl, pi * 96, pj * 96, pair != 1,
                                        &g_GpT[seg][bw][0], sb);
    } else {
        int r0 = bid - NBLK_T;
        int seg = r0 / 48, r = r0 % 48, bw = r / 3, pair = r % 3;
        int which = bw >> 3, b = bw & 7;
        int pi = (pair == 2) ? 1 : 0, pj = (pair == 0) ? 0 : 1;
        const ush* gh = g_Th[which] + (size_t)(b * 384 + seg * 64) * (LFm * 32);
        const ush* gl = g_Tl[which] + (size_t)(b * 384 + seg * 64) * (LFm * 32);
        gram_body<LFm, 64, 2, 2, 32, 2>(gh, gl, pi * 64, pj * 64, pair != 1,
                                        &g_GpF[seg][bw][0], sb);
    }
}

// ---------------- 3) sum partials + mirror + fused norms ----------------
__global__ void sumG_kernel() {
    int idx = blockIdx.x * 256 + threadIdx.x;
    if (idx < NT_E) {
        int bw = idx / (LTm * LTm), e = idx % (LTm * LTm);
        int i = e / LTm, j = e % LTm;
        int es = (i >= 96 && j < 96) ? (j * LTm + i) : e;
        float s = 0.f;
#pragma unroll
        for (int g = 0; g < SEGS_T; g++) s += g_GpT[g][bw][es];
        int which = bw >> 3, b = bw & 7;
        g_G[0][which][(size_t)b * LTm * LTm + e] = s;
        if (i == j) g_inv[0][which][b * LTm + i] = 1.0f / fmaxf(sqrtf(s), 1e-8f);
    } else {
        idx -= NT_E;
        int bw = idx / (LFm * LFm), e = idx % (LFm * LFm);
        int i = e / LFm, j = e % LFm;
        int es = (i >= 64 && j < 64) ? (j * LFm + i) : e;
        float s = 0.f;
#pragma unroll
        for (int g = 0; g < SEGS_F; g++) s += g_GpF[g][bw][es];
        int which = bw >> 3, b = bw & 7;
        g_G[1][which][(size_t)b * LFm * LFm + e] = s;
        if (i == j) g_inv[1][which][b * LFm + i] = 1.0f / fmaxf(sqrtf(s), 1e-8f);
    }
}

// ---------------- 4) rowproc: warp-per-row, both views, no barriers ----------------
__global__ void rowproc2_kernel() {
    int w = blockIdx.x * 8 + (threadIdx.x >> 5);
    int lane = threadIdx.x & 31;
    int view, which, b, l, L;
    if (w < 3072) { view = 0; L = 192; which = w / 1536; int r = w % 1536; b = r / 192; l = r % 192; }
    else { int w2 = w - 3072; view = 1; L = 128; which = w2 / 1024; int r = w2 % 1024; b = r / 128; l = r % 128; }
    float* G = g_G[view][which] + ((size_t)b * L + l) * L;
    const float* inv = g_inv[view][which] + b * L;
    float invl = inv[l];
    int ne = L >> 5;
    float pv[6];
    float s = 0.f, mx = -3.402823466e38f;
    for (int e = 0; e < ne; e++) {
        int m = lane + e * 32;
        pv[e] = 0.5f * (G[m] * invl * inv[m] + 1.0f);
        s += pv[e];
        mx = fmaxf(mx, pv[e]);
    }
    s = warpSum(s);
    mx = warpMax(mx);
    if (lane == 0) g_mean[view][which][b * L + l] = s / (float)L;
    float ex[6], Z = 0.f;
    for (int e = 0; e < ne; e++) { ex[e] = expf(pv[e] - mx); Z += ex[e]; }
    Z = warpSum(Z);
    float ent = 0.f;
    for (int e = 0; e < ne; e++) {
        int m = lane + e * 32;
        float sp = ex[e] / Z + 1e-8f;
        if (which == 0) G[m] = logf(sp + 1e-8f);
        else { G[m] = sp; ent += sp * logf(sp + 1e-8f); }
    }
    if (which == 1) {
        ent = warpSum(ent);
        if (lane == 0) g_ent[view][b * L + l] = ent;
    }
}

// ---------------- 5) MLP (both views) ----------------
__global__ void mlp_kernel(const float* __restrict__ WqT, const float* __restrict__ bqT,
                           const float* __restrict__ gqT, const float* __restrict__ BqT,
                           const float* __restrict__ WkT, const float* __restrict__ bkT,
                           const float* __restrict__ gkT, const float* __restrict__ BkT,
                           const float* __restrict__ WqF, const float* __restrict__ bqF,
                           const float* __restrict__ gqF, const float* __restrict__ BqF,
                           const float* __restrict__ WkF, const float* __restrict__ bkF,
                           const float* __restrict__ gkF, const float* __restrict__ BkF) {
    int b = blockIdx.x, sel = blockIdx.y, view = blockIdx.z;
    int L = view ? LFm : LTm;
    int l = threadIdx.x;
    if (l >= L) return;
    const float* W  = view ? (sel ? WkF : WqF) : (sel ? WkT : WqT);
    const float* bi = view ? (sel ? bkF : bqF) : (sel ? bkT : bqT);
    const float* gg = view ? (sel ? gkF : gqF) : (sel ? gkT : gqT);
    const float* be = view ? (sel ? BkF : BqF) : (sel ? BkT : BqT);
    float x = g_mean[view][sel][b * L + l];
    float h[HH]; float mu = 0.f;
#pragma unroll
    for (int j = 0; j < HH; j++) { h[j] = fmaxf(W[j] * x + bi[j], 0.f); mu += h[j]; }
    mu *= (1.0f / HH);
    float var = 0.f;
#pragma unroll
    for (int j = 0; j < HH; j++) { float d = h[j] - mu; var += d * d; }
    var *= (1.0f / HH);
    float inv = rsqrtf(var + 1e-5f);
#pragma unroll
    for (int j = 0; j < HH; j++)
        g_qk[view][sel][((size_t)b * L + l) * HH + j] = gg[j] * (h[j] - mu) * inv + be[j];
}

// ---------------- 6) alpha + fused ent-dot (both views) ----------------
__global__ void alpha_kernel() {
    __shared__ float kb[LTm * HH];
    __shared__ float red[8];
    int s = blockIdx.x, b = blockIdx.y, view = blockIdx.z;
    int L = view ? LFm : LTm;
    if (s >= L) return;
    int t = threadIdx.x;
    for (int i = t; i < L * HH; i += blockDim.x)
        kb[i] = g_qk[view][1][(size_t)b * L * HH + i];
    float q0 = g_qk[view][0][((size_t)b * L + s) * HH + 0];
    float q1 = g_qk[view][0][((size_t)b * L + s) * HH + 1];
    float q2 = g_qk[view][0][((size_t)b * L + s) * HH + 2];
    float q3 = g_qk[view][0][((size_t)b * L + s) * HH + 3];
    __syncthreads();
    float a = -3.402823466e38f;
    if (t < L) {
        float invScale = rsqrtf(4.0f + 1e-8f);
        a = (q0 * kb[t * 4 + 0] + q1 * kb[t * 4 + 1] + q2 * kb[t * 4 + 2] + q3 * kb[t * 4 + 3]) * invScale;
    }
    float mx = blockMax(a, red);
    float e = (t < L) ? expf(a - mx) : 0.f;
    float Z = blockSum(e, red);
    float al = e / Z;
    if (t < L) g_alpha[view][(size_t)b * L * L + (size_t)s * L + t] = al;
    float rd = blockSum((t < L) ? al * g_ent[view][b * L + t] : 0.f, red);
    if (t == 0) g_rowdot[view][b * L + s] = rd;
}

// ---------------- 7) term2 partials (both views) ----------------
__global__ void part_kernel() {
    __shared__ float salT[LTm][8];
    __shared__ float red[8];
    int view = blockIdx.z, b = blockIdx.y;
    int L = view ? LFm : LTm;
    if (blockIdx.x * 8 >= L) {
        if (threadIdx.x == 0) g_part[view][b * 24 + blockIdx.x] = 0.f;
        return;
    }
    int s0 = blockIdx.x * 8;
    const float* logPs = g_G[view][0] + (size_t)b * L * L;
    const float* Pt    = g_G[view][1] + (size_t)b * L * L;
    const float* al    = g_alpha[view] + (size_t)b * L * L;
    int k = threadIdx.x;
    if (k < L) {
#pragma unroll
        for (int i = 0; i < 8; i++) salT[k][i] = al[(size_t)(s0 + i) * L + k];
    }
    __syncthreads();
    float m[8];
#pragma unroll
    for (int i = 0; i < 8; i++) m[i] = 0.f;
    int kc = (k < L) ? k : 0;
#pragma unroll 2
    for (int t = 0; t < L; t++) {
        float4 a0 = *(const float4*)&salT[t][0];
        float4 a1 = *(const float4*)&salT[t][4];
        float pv = Pt[(size_t)t * L + kc];
        m[0] += a0.x * pv; m[1] += a0.y * pv; m[2] += a0.z * pv; m[3] += a0.w * pv;
        m[4] += a1.x * pv; m[5] += a1.y * pv; m[6] += a1.z * pv; m[7] += a1.w * pv;
    }
    float acc = 0.f;
    if (k < L) {
#pragma unroll
        for (int i = 0; i < 8; i++) acc += m[i] * logPs[(size_t)(s0 + i) * L + k];
    }
    float tot = blockSum(acc, red);
    if (k == 0) g_part[view][b * 24 + blockIdx.x] = tot;
}

// ---------------- 8) final reduction ----------------
__global__ void final_kernel(float* out) {
    __shared__ float red[8];
    int tid = threadIdx.x;
    float t2T = 0.f; for (int i = tid; i < 24 * BB; i += 256) t2T += g_part[0][i];
    t2T = blockSum(t2T, red);
    float t2F = 0.f; for (int i = tid; i < 24 * BB; i += 256) t2F += g_part[1][i];
    t2F = blockSum(t2F, red);
    float t1T = 0.f; for (int i = tid; i < BB * LTm; i += 256) t1T += g_rowdot[0][i];
    t1T = blockSum(t1T, red);
    float t1F = 0.f; for (int i = tid; i < BB * LFm; i += 256) t1F += g_rowdot[1][i];
    t1F = blockSum(t1F, red);
    if (tid == 0) {
        float lt = (t1T - t2T) / ((float)BB * LTm * LTm + 1e-8f);
        float lf = (t1F - t2F) / ((float)BB * LFm * LFm + 1e-8f);
        out[0] = lt + lf;
    }
}

// ---------------- launch ----------------
extern "C" void kernel_launch(void* const* d_in, const int* in_sizes, int n_in,
                              void* d_out, int out_size) {
    const float* fs  = (const float*)d_in[0];
    const float* ft  = (const float*)d_in[1];
    float* out = (float*)d_out;

    cudaFuncSetAttribute(gram_kernel, cudaFuncAttributeMaxDynamicSharedMemorySize, 98304);

    prep_kernel<<<dim3(TT / 32, FFR / 32, BB * CC * 2), dim3(32, 8)>>>(fs, ft);

    gram_kernel<<<NBLK_T + NBLK_F, 128, 98304>>>();

    sumG_kernel<<<(NT_E + NF_E) / 256, 256>>>();

    rowproc2_kernel<<<640, 256>>>();

    mlp_kernel<<<dim3(BB, 2, 2), 192>>>(
        (const float*)d_in[2], (const float*)d_in[3], (const float*)d_in[4], (const float*)d_in[5],
        (const float*)d_in[6], (const float*)d_in[7], (const float*)d_in[8], (const float*)d_in[9],
        (const float*)d_in[10], (const float*)d_in[11], (const float*)d_in[12], (const float*)d_in[13],
        (const float*)d_in[14], (const float*)d_in[15], (const float*)d_in[16], (const float*)d_in[17]);

    alpha_kernel<<<dim3(LTm, BB, 2), 192>>>();

    part_kernel<<<dim3(24, BB, 2), 192>>>();

    final_kernel<<<1, 256>>>(out);
}